// round 12
// baseline (speedup 1.0000x reference)
#include <cuda_runtime.h>
#include <math.h>

#define NN   256      // total graph nodes
#define FDIM 1024
#define HIDD 512
#define NH   4
#define DD2  256
#define HD1  2048     // NH*HIDD
#define HD2  1024     // NH*DD2

typedef unsigned long long ull;

// ---- device scratch (no allocations allowed) ----
__device__ float g_xl1[NN * HD1];
__device__ float g_xr1[NN * HD1];
__device__ float g_o1 [NN * HD1];
__device__ float g_xl2[NN * HD2];
__device__ float g_xr2[NN * HD2];
__device__ float g_o2 [NN * HD2];
__device__ float g_s  [NH * NN * NN];   // attention scores / weights
__device__ float g_al [NH * NN];        // att . xl per (head, node)
__device__ float g_part[1 << 21];       // 8 MB split-K partials

// ---- packed f32x2 helpers (PTX-only path; ptxas never emits these) ----
__device__ __forceinline__ ull dupf(float x) {
    ull r;
    asm("mov.b64 %0, {%1, %1};" : "=l"(r) : "f"(x));
    return r;
}
__device__ __forceinline__ void fma2(ull& acc, ull a, ull b) {
    asm("fma.rn.f32x2 %0, %1, %2, %0;" : "+l"(acc) : "l"(a), "l"(b));
}
__device__ __forceinline__ ull add2(ull a, ull b) {
    ull r;
    asm("add.rn.f32x2 %0, %1, %2;" : "=l"(r) : "l"(a), "l"(b));
    return r;
}
__device__ __forceinline__ float2 unpk(ull v) {
    float2 r;
    asm("mov.b64 {%0, %1}, %2;" : "=f"(r.x), "=f"(r.y) : "l"(v));
    return r;
}
#define ABS2(v) ((v) & 0x7FFFFFFF7FFFFFFFull)

// ------- pipelined fp32 GEMM, 128x64 tile, BK=16, split-K, dual-GEMM, FFMA2 -----
__global__ __launch_bounds__(256)
void gemm_pipe(const float* __restrict__ A,
               const float* __restrict__ I0, const float* __restrict__ I1,
               const float* __restrict__ I2, const float* __restrict__ I3,
               const float* __restrict__ W0, const float* __restrict__ W1,
               int M, int K, int N, int splitk, int fromInputs) {
    const int z = blockIdx.z;
    const int g = z / splitk;
    const int s = z % splitk;
    const float* W = g ? W1 : W0;
    const int kspan = K / splitk;
    const int kbeg  = s * kspan;
    const int nIters = kspan / 16;

    __shared__ __align__(16) float As[2][16][132];
    __shared__ __align__(16) float Ws[2][16][64];

    const int brow = blockIdx.y * 128;
    const int bcol = blockIdx.x * 64;
    const int tid  = threadIdx.x;
    const int tx   = tid & 15;        // 4 cols at tx*4
    const int ty   = tid >> 4;        // 8 rows at ty*8

    const int am0 = tid >> 2;                 // 0..63
    const int ak0 = (tid & 3) * 4;            // 0,4,8,12
    const int am1 = am0 + 64;
    const int wk = tid >> 4;
    const int wn = (tid & 15) * 4;

    const int r0 = brow + am0, r1 = brow + am1;
    const float* Ap0;
    const float* Ap1;
    if (fromInputs) {
        const float* b0 = (r0 < 64) ? I0 : (r0 < 128) ? I1 : (r0 < 192) ? I2 : I3;
        const float* b1 = (r1 < 64) ? I0 : (r1 < 128) ? I1 : (r1 < 192) ? I2 : I3;
        Ap0 = b0 + (size_t)(r0 & 63) * K + kbeg + ak0;
        Ap1 = b1 + (size_t)(r1 & 63) * K + kbeg + ak0;
    } else {
        Ap0 = A + (size_t)r0 * K + kbeg + ak0;
        Ap1 = A + (size_t)r1 * K + kbeg + ak0;
    }
    const float* Wp = W + (size_t)(kbeg + wk) * N + bcol + wn;

    ull acc[4][4];   // [i-pair][j]
#pragma unroll
    for (int i = 0; i < 4; i++)
#pragma unroll
        for (int j = 0; j < 4; j++) acc[i][j] = 0ull;

    {
        float4 ra0 = *reinterpret_cast<const float4*>(Ap0);
        float4 ra1 = *reinterpret_cast<const float4*>(Ap1);
        float4 rw  = *reinterpret_cast<const float4*>(Wp);
        As[0][ak0 + 0][am0] = ra0.x;
        As[0][ak0 + 1][am0] = ra0.y;
        As[0][ak0 + 2][am0] = ra0.z;
        As[0][ak0 + 3][am0] = ra0.w;
        As[0][ak0 + 0][am1] = ra1.x;
        As[0][ak0 + 1][am1] = ra1.y;
        As[0][ak0 + 2][am1] = ra1.z;
        As[0][ak0 + 3][am1] = ra1.w;
        *reinterpret_cast<float4*>(&Ws[0][wk][wn]) = rw;
    }
    __syncthreads();

    int buf = 0;
    for (int it = 0; it < nIters; it++) {
        const bool has_next = (it + 1) < nIters;
        float4 ra0, ra1, rw;
        if (has_next) {
            const int ko = (it + 1) * 16;
            ra0 = *reinterpret_cast<const float4*>(Ap0 + ko);
            ra1 = *reinterpret_cast<const float4*>(Ap1 + ko);
            rw  = *reinterpret_cast<const float4*>(Wp + (size_t)ko * N);
        }
#pragma unroll
        for (int kk = 0; kk < 16; kk++) {
            ulonglong2 aP01 = *reinterpret_cast<const ulonglong2*>(&As[buf][kk][ty * 8]);
            ulonglong2 aP23 = *reinterpret_cast<const ulonglong2*>(&As[buf][kk][ty * 8 + 4]);
            float4 wv = *reinterpret_cast<const float4*>(&Ws[buf][kk][tx * 4]);
            ull w0 = dupf(wv.x);
            ull w1 = dupf(wv.y);
            ull w2 = dupf(wv.z);
            ull w3 = dupf(wv.w);
            fma2(acc[0][0], aP01.x, w0); fma2(acc[0][1], aP01.x, w1);
            fma2(acc[0][2], aP01.x, w2); fma2(acc[0][3], aP01.x, w3);
            fma2(acc[1][0], aP01.y, w0); fma2(acc[1][1], aP01.y, w1);
            fma2(acc[1][2], aP01.y, w2); fma2(acc[1][3], aP01.y, w3);
            fma2(acc[2][0], aP23.x, w0); fma2(acc[2][1], aP23.x, w1);
            fma2(acc[2][2], aP23.x, w2); fma2(acc[2][3], aP23.x, w3);
            fma2(acc[3][0], aP23.y, w0); fma2(acc[3][1], aP23.y, w1);
            fma2(acc[3][2], aP23.y, w2); fma2(acc[3][3], aP23.y, w3);
        }
        if (has_next) {
            int nb = buf ^ 1;
            As[nb][ak0 + 0][am0] = ra0.x;
            As[nb][ak0 + 1][am0] = ra0.y;
            As[nb][ak0 + 2][am0] = ra0.z;
            As[nb][ak0 + 3][am0] = ra0.w;
            As[nb][ak0 + 0][am1] = ra1.x;
            As[nb][ak0 + 1][am1] = ra1.y;
            As[nb][ak0 + 2][am1] = ra1.z;
            As[nb][ak0 + 3][am1] = ra1.w;
            *reinterpret_cast<float4*>(&Ws[nb][wk][wn]) = rw;
            __syncthreads();
            buf = nb;
        }
    }

    float* P = g_part + (size_t)z * M * N;
    const int n = bcol + tx * 4;
#pragma unroll
    for (int ip = 0; ip < 4; ip++) {
        float2 c0 = unpk(acc[ip][0]);
        float2 c1 = unpk(acc[ip][1]);
        float2 c2 = unpk(acc[ip][2]);
        float2 c3 = unpk(acc[ip][3]);
        int m0 = brow + ty * 8 + 2 * ip;
        float4 rr0; rr0.x = c0.x; rr0.y = c1.x; rr0.z = c2.x; rr0.w = c3.x;
        float4 rr1; rr1.x = c0.y; rr1.y = c1.y; rr1.z = c2.y; rr1.w = c3.y;
        *reinterpret_cast<float4*>(&P[(size_t)m0 * N + n])       = rr0;
        *reinterpret_cast<float4*>(&P[(size_t)(m0 + 1) * N + n]) = rr1;
    }
}

// ---- split-K reduce + bias + fused al = att.xl per (head, node) ----
__global__ __launch_bounds__(256)
void reduce_al1(const float* __restrict__ b0, const float* __restrict__ b1,
                const float* __restrict__ att) {
    const int n = blockIdx.x;
    const int tid = threadIdx.x;
    const int lane = tid & 31, w = tid >> 5;
    const int MN = NN * HD1;
    const size_t ro = (size_t)n * HD1;
    __shared__ float sred[8];

    float alp = 0.f;
#pragma unroll
    for (int q = 0; q < 2; q++) {
        int c = tid * 8 + q * 4;
        float4 p0 = *reinterpret_cast<const float4*>(&g_part[ro + c]);
        float4 p1 = *reinterpret_cast<const float4*>(&g_part[MN + ro + c]);
        float4 bb = *reinterpret_cast<const float4*>(&b0[c]);
        float4 v;
        v.x = p0.x + p1.x + bb.x;
        v.y = p0.y + p1.y + bb.y;
        v.z = p0.z + p1.z + bb.z;
        v.w = p0.w + p1.w + bb.w;
        *reinterpret_cast<float4*>(&g_xl1[ro + c]) = v;
        float4 at = *reinterpret_cast<const float4*>(&att[c]);
        alp = fmaf(at.x, v.x, alp);
        alp = fmaf(at.y, v.y, alp);
        alp = fmaf(at.z, v.z, alp);
        alp = fmaf(at.w, v.w, alp);

        float4 q0 = *reinterpret_cast<const float4*>(&g_part[2 * (size_t)MN + ro + c]);
        float4 q1 = *reinterpret_cast<const float4*>(&g_part[3 * (size_t)MN + ro + c]);
        float4 b2 = *reinterpret_cast<const float4*>(&b1[c]);
        float4 u;
        u.x = q0.x + q1.x + b2.x;
        u.y = q0.y + q1.y + b2.y;
        u.z = q0.z + q1.z + b2.z;
        u.w = q0.w + q1.w + b2.w;
        *reinterpret_cast<float4*>(&g_xr1[ro + c]) = u;
    }
#pragma unroll
    for (int o = 16; o; o >>= 1) alp += __shfl_xor_sync(0xffffffffu, alp, o);
    if (lane == 0) sred[w] = alp;
    __syncthreads();
    if (tid < 4) g_al[tid * NN + n] = sred[2 * tid] + sred[2 * tid + 1];
}

__global__ __launch_bounds__(256)
void reduce_al2(const float* __restrict__ b0, const float* __restrict__ b1,
                const float* __restrict__ att) {
    const int n = blockIdx.x;
    const int tid = threadIdx.x;
    const int lane = tid & 31, w = tid >> 5;
    const int MN = NN * HD2;
    const size_t ro = (size_t)n * HD2;
    __shared__ float sred[8];

    int c = tid * 4;
    float4 p0 = *reinterpret_cast<const float4*>(&g_part[ro + c]);
    float4 p1 = *reinterpret_cast<const float4*>(&g_part[(size_t)MN + ro + c]);
    float4 p2 = *reinterpret_cast<const float4*>(&g_part[2 * (size_t)MN + ro + c]);
    float4 p3 = *reinterpret_cast<const float4*>(&g_part[3 * (size_t)MN + ro + c]);
    float4 bb = *reinterpret_cast<const float4*>(&b0[c]);
    float4 v;
    v.x = p0.x + p1.x + p2.x + p3.x + bb.x;
    v.y = p0.y + p1.y + p2.y + p3.y + bb.y;
    v.z = p0.z + p1.z + p2.z + p3.z + bb.z;
    v.w = p0.w + p1.w + p2.w + p3.w + bb.w;
    *reinterpret_cast<float4*>(&g_xl2[ro + c]) = v;
    float4 at = *reinterpret_cast<const float4*>(&att[c]);
    float alp = at.x * v.x + at.y * v.y + at.z * v.z + at.w * v.w;

    float4 q0 = *reinterpret_cast<const float4*>(&g_part[4 * (size_t)MN + ro + c]);
    float4 q1 = *reinterpret_cast<const float4*>(&g_part[5 * (size_t)MN + ro + c]);
    float4 q2 = *reinterpret_cast<const float4*>(&g_part[6 * (size_t)MN + ro + c]);
    float4 q3 = *reinterpret_cast<const float4*>(&g_part[7 * (size_t)MN + ro + c]);
    float4 b2 = *reinterpret_cast<const float4*>(&b1[c]);
    float4 u;
    u.x = q0.x + q1.x + q2.x + q3.x + b2.x;
    u.y = q0.y + q1.y + q2.y + q3.y + b2.y;
    u.z = q0.z + q1.z + q2.z + q3.z + b2.z;
    u.w = q0.w + q1.w + q2.w + q3.w + b2.w;
    *reinterpret_cast<float4*>(&g_xr2[ro + c]) = u;

#pragma unroll
    for (int o = 16; o; o >>= 1) alp += __shfl_xor_sync(0xffffffffu, alp, o);
    if (lane == 0) sred[w] = alp;
    __syncthreads();
    if (tid < 4) g_al[tid * NN + n] = sred[2 * tid] + sred[2 * tid + 1];
}

// ------- GATv2 scores: 32i x 64j tile (proven shape), packed f32x2 inner math ----
// lrelu(z,0.2) = 0.6 z + 0.4 |z|; the 0.6*ar_i term cancels in softmax.
// s[h,i,j] = 0.6*al[h,j] + sum_d (0.4*att[h,d])*|xr_i+xl_j|
template <int D>
__global__ __launch_bounds__(256)
void gat_scores(const float* __restrict__ xl, const float* __restrict__ xr,
                const float* __restrict__ att, float* __restrict__ s_out) {
    const int HD = NH * D;
    const int j0 = blockIdx.x * 64;
    const int i0 = blockIdx.y * 32;
    const int h  = blockIdx.z;
    const int tid = threadIdx.x;
    const int tx = tid & 15, ty = tid >> 4;    // thread -> 2 i's (ty*2), 4 j's (tx*4)

    __shared__ __align__(16) float s_xr[64][34];   // [d][i], 136B rows (8B-aligned)
    __shared__ __align__(16) float s_xl[64][68];   // [d][j], 272B rows (16B-aligned)
    __shared__ ull s_attP[D];

    for (int d = tid; d < D; d += 256) s_attP[d] = dupf(0.4f * att[h * D + d]);

    ull acc[2][2];
    acc[0][0] = acc[0][1] = acc[1][0] = acc[1][1] = 0ull;

    for (int d0 = 0; d0 < D; d0 += 64) {
        // xr: 32 rows x 64 d (coalesced, 16 threads per row)
#pragma unroll
        for (int r = 0; r < 2; r++) {
            int idx = tid + r * 256;
            int row = idx >> 4;
            int kk  = (idx & 15) * 4;
            float4 v = *reinterpret_cast<const float4*>(
                &xr[(size_t)(i0 + row) * HD + h * D + d0 + kk]);
            s_xr[kk + 0][row] = v.x;
            s_xr[kk + 1][row] = v.y;
            s_xr[kk + 2][row] = v.z;
            s_xr[kk + 3][row] = v.w;
        }
        // xl: 64 rows x 64 d
#pragma unroll
        for (int r = 0; r < 4; r++) {
            int idx = tid + r * 256;
            int row = idx >> 4;
            int kk  = (idx & 15) * 4;
            float4 v = *reinterpret_cast<const float4*>(
                &xl[(size_t)(j0 + row) * HD + h * D + d0 + kk]);
            s_xl[kk + 0][row] = v.x;
            s_xl[kk + 1][row] = v.y;
            s_xl[kk + 2][row] = v.z;
            s_xl[kk + 3][row] = v.w;
        }
        __syncthreads();
#pragma unroll 8
        for (int kk = 0; kk < 64; kk++) {
            ull attP = s_attP[d0 + kk];
            float2 xrP = *reinterpret_cast<const float2*>(&s_xr[kk][ty * 2]);
            ulonglong2 xlP = *reinterpret_cast<const ulonglong2*>(&s_xl[kk][tx * 4]);
            ull x0 = dupf(xrP.x);
            ull x1 = dupf(xrP.y);
            fma2(acc[0][0], attP, ABS2(add2(x0, xlP.x)));
            fma2(acc[0][1], attP, ABS2(add2(x0, xlP.y)));
            fma2(acc[1][0], attP, ABS2(add2(x1, xlP.x)));
            fma2(acc[1][1], attP, ABS2(add2(x1, xlP.y)));
        }
        __syncthreads();
    }

    float4 alv = *reinterpret_cast<const float4*>(&g_al[h * NN + j0 + tx * 4]);
#pragma unroll
    for (int ii = 0; ii < 2; ii++) {
        int i = i0 + ty * 2 + ii;
        int jb = j0 + tx * 4;
        float2 a0 = unpk(acc[ii][0]);
        float2 a1 = unpk(acc[ii][1]);
        float4 o;
        o.x = fmaf(0.6f, alv.x, a0.x);
        o.y = fmaf(0.6f, alv.y, a0.y);
        o.z = fmaf(0.6f, alv.z, a1.x);
        o.w = fmaf(0.6f, alv.w, a1.y);
        if (i - jb >= 0 && i - jb < 4) {
            if (i == jb + 0) o.x = -INFINITY;
            if (i == jb + 1) o.y = -INFINITY;
            if (i == jb + 2) o.z = -INFINITY;
            if (i == jb + 3) o.w = -INFINITY;
        }
        *reinterpret_cast<float4*>(&s_out[((size_t)h * NN + i) * NN + jb]) = o;
    }
}

// ---------------- softmax: warp per row, 8 rows per CTA ----------------
__global__ __launch_bounds__(256)
void gat_softmax(float* __restrict__ s) {
    const int row = blockIdx.x * 8 + (threadIdx.x >> 5);
    const int lane = threadIdx.x & 31;
    float* r = s + (size_t)row * NN;

    float4 v0 = *reinterpret_cast<const float4*>(&r[lane * 8]);
    float4 v1 = *reinterpret_cast<const float4*>(&r[lane * 8 + 4]);
    float m = fmaxf(fmaxf(fmaxf(v0.x, v0.y), fmaxf(v0.z, v0.w)),
                    fmaxf(fmaxf(v1.x, v1.y), fmaxf(v1.z, v1.w)));
#pragma unroll
    for (int o = 16; o; o >>= 1) m = fmaxf(m, __shfl_xor_sync(0xffffffffu, m, o));
    v0.x = expf(v0.x - m); v0.y = expf(v0.y - m);
    v0.z = expf(v0.z - m); v0.w = expf(v0.w - m);
    v1.x = expf(v1.x - m); v1.y = expf(v1.y - m);
    v1.z = expf(v1.z - m); v1.w = expf(v1.w - m);
    float ss = v0.x + v0.y + v0.z + v0.w + v1.x + v1.y + v1.z + v1.w;
#pragma unroll
    for (int o = 16; o; o >>= 1) ss += __shfl_xor_sync(0xffffffffu, ss, o);
    float inv = 1.f / ss;
    v0.x *= inv; v0.y *= inv; v0.z *= inv; v0.w *= inv;
    v1.x *= inv; v1.y *= inv; v1.z *= inv; v1.w *= inv;
    *reinterpret_cast<float4*>(&r[lane * 8])     = v0;
    *reinterpret_cast<float4*>(&r[lane * 8 + 4]) = v1;
}

// ---- aggregation GEMM per head: 64x64 tile, 4i x 4j per thread, FFMA2 ----
template <int D, int ACT>
__global__ __launch_bounds__(256)
void gat_agg(const float* __restrict__ a, const float* __restrict__ xl,
             const float* __restrict__ bias, float* __restrict__ out) {
    const int HD = NH * D;
    const int h = blockIdx.z;
    const int brow = blockIdx.y * 64;
    const int bcol = blockIdx.x * 64;
    const float* A = a + (size_t)h * NN * NN;
    const float* B = xl + h * D;

    __shared__ __align__(16) float As[2][32][68];   // k-major A (i contiguous)
    __shared__ __align__(16) float Ws[2][32][64];

    const int tid = threadIdx.x;
    const int tx = tid & 15;          // 4 j's at tx*4
    const int ty = tid >> 4;          // 4 i's at ty*4

    const int aIdx0 = tid * 4;                // 0..1020
    const int am0 = aIdx0 >> 5, ak0 = aIdx0 & 31;   // rows 0..31
    const int am1 = am0 + 32;                        // rows 32..63
    const int wk0 = tid >> 4;                 // rows 0..15
    const int wk1 = wk0 + 16;                 // rows 16..31
    const int wn  = (tid & 15) * 4;

    const float* Ap0 = A + (size_t)(brow + am0) * NN + ak0;
    const float* Ap1 = A + (size_t)(brow + am1) * NN + ak0;
    const float* Bp0 = B + (size_t)wk0 * HD + bcol + wn;
    const float* Bp1 = B + (size_t)wk1 * HD + bcol + wn;

    ull acc[4][2];   // [i][j-pair]
#pragma unroll
    for (int i = 0; i < 4; i++) { acc[i][0] = 0ull; acc[i][1] = 0ull; }

    {
        float4 ra0 = *reinterpret_cast<const float4*>(Ap0);
        float4 ra1 = *reinterpret_cast<const float4*>(Ap1);
        float4 rw0 = *reinterpret_cast<const float4*>(Bp0);
        float4 rw1 = *reinterpret_cast<const float4*>(Bp1);
        As[0][ak0 + 0][am0] = ra0.x;
        As[0][ak0 + 1][am0] = ra0.y;
        As[0][ak0 + 2][am0] = ra0.z;
        As[0][ak0 + 3][am0] = ra0.w;
        As[0][ak0 + 0][am1] = ra1.x;
        As[0][ak0 + 1][am1] = ra1.y;
        As[0][ak0 + 2][am1] = ra1.z;
        As[0][ak0 + 3][am1] = ra1.w;
        *reinterpret_cast<float4*>(&Ws[0][wk0][wn]) = rw0;
        *reinterpret_cast<float4*>(&Ws[0][wk1][wn]) = rw1;
    }
    __syncthreads();

    int buf = 0;
    const int nIters = NN / 32;   // 8
    for (int it = 0; it < nIters; it++) {
        const bool has_next = (it + 1) < nIters;
        float4 ra0, ra1, rw0, rw1;
        if (has_next) {
            const int ko = (it + 1) * 32;
            ra0 = *reinterpret_cast<const float4*>(Ap0 + ko);
            ra1 = *reinterpret_cast<const float4*>(Ap1 + ko);
            rw0 = *reinterpret_cast<const float4*>(Bp0 + (size_t)ko * HD);
            rw1 = *reinterpret_cast<const float4*>(Bp1 + (size_t)ko * HD);
        }
#pragma unroll
        for (int kk = 0; kk < 32; kk++) {
            float4 av = *reinterpret_cast<const float4*>(&As[buf][kk][ty * 4]);
            ulonglong2 wP = *reinterpret_cast<const ulonglong2*>(&Ws[buf][kk][tx * 4]);
            ull a0 = dupf(av.x);
            ull a1 = dupf(av.y);
            ull a2 = dupf(av.z);
            ull a3 = dupf(av.w);
            fma2(acc[0][0], a0, wP.x); fma2(acc[0][1], a0, wP.y);
            fma2(acc[1][0], a1, wP.x); fma2(acc[1][1], a1, wP.y);
            fma2(acc[2][0], a2, wP.x); fma2(acc[2][1], a2, wP.y);
            fma2(acc[3][0], a3, wP.x); fma2(acc[3][1], a3, wP.y);
        }
        if (has_next) {
            int nb = buf ^ 1;
            As[nb][ak0 + 0][am0] = ra0.x;
            As[nb][ak0 + 1][am0] = ra0.y;
            As[nb][ak0 + 2][am0] = ra0.z;
            As[nb][ak0 + 3][am0] = ra0.w;
            As[nb][ak0 + 0][am1] = ra1.x;
            As[nb][ak0 + 1][am1] = ra1.y;
            As[nb][ak0 + 2][am1] = ra1.z;
            As[nb][ak0 + 3][am1] = ra1.w;
            *reinterpret_cast<float4*>(&Ws[nb][wk0][wn]) = rw0;
            *reinterpret_cast<float4*>(&Ws[nb][wk1][wn]) = rw1;
            __syncthreads();
            buf = nb;
        }
    }

    const int n = bcol + tx * 4;
    float4 bv = *reinterpret_cast<const float4*>(&bias[h * D + n]);
#pragma unroll
    for (int i = 0; i < 4; i++) {
        int m = brow + ty * 4 + i;
        float2 lo = unpk(acc[i][0]);
        float2 hi = unpk(acc[i][1]);
        float4 o;
        o.x = lo.x + bv.x;
        o.y = lo.y + bv.y;
        o.z = hi.x + bv.z;
        o.w = hi.y + bv.w;
        if (ACT == 1) {
            o.x = o.x > 0.f ? o.x : expm1f(o.x);
            o.y = o.y > 0.f ? o.y : expm1f(o.y);
            o.z = o.z > 0.f ? o.z : expm1f(o.z);
            o.w = o.w > 0.f ? o.w : expm1f(o.w);
        }
        *reinterpret_cast<float4*>(&out[(size_t)m * HD + h * D + n]) = o;
    }
}

// ------- LayerNorm + ReLU + residual, rows 0..127; sums Wout's 16 split-K partials
__global__ __launch_bounds__(256)
void ln_residual(const float* __restrict__ bout,
                 const float* __restrict__ ln_g, const float* __restrict__ ln_b,
                 const float* __restrict__ rw,
                 const float* __restrict__ v1f, const float* __restrict__ v2f,
                 float* __restrict__ out) {
    const int i = blockIdx.x;
    const int tid = threadIdx.x;
    const int lane = tid & 31, warp = tid >> 5;
    const int MN = 128 * FDIM;
    __shared__ float s_red1[8], s_red2[8];
    __shared__ float s_mu, s_rstd;

    const float* res = (i < 64) ? (v1f + (size_t)i * FDIM)
                                : (v2f + (size_t)(i - 64) * FDIM);

    float yv[4];
    float sum = 0.f, sq = 0.f;
#pragma unroll
    for (int q = 0; q < 4; q++) {
        int c = tid + q * 256;
        float v = bout[c];
#pragma unroll
        for (int s = 0; s < 16; s++)
            v += g_part[(size_t)s * MN + i * FDIM + c];
        yv[q] = v;
        sum += v; sq += v * v;
    }
#pragma unroll
    for (int o = 16; o; o >>= 1) {
        sum += __shfl_xor_sync(0xffffffffu, sum, o);
        sq  += __shfl_xor_sync(0xffffffffu, sq,  o);
    }
    if (lane == 0) { s_red1[warp] = sum; s_red2[warp] = sq; }
    __syncthreads();
    if (tid == 0) {
        float ts = 0.f, tq = 0.f;
        for (int w = 0; w < 8; w++) { ts += s_red1[w]; tq += s_red2[w]; }
        float mu = ts / FDIM;
        float var = tq / FDIM - mu * mu;
        s_mu = mu;
        s_rstd = rsqrtf(var + 1e-5f);
    }
    __syncthreads();
    float mu = s_mu, rstd = s_rstd, w0 = rw[0];
#pragma unroll
    for (int q = 0; q < 4; q++) {
        int c = tid + q * 256;
        float v = (yv[q] - mu) * rstd * ln_g[c] + ln_b[c];
        v = fmaxf(v, 0.f);
        out[i * FDIM + c] = v + w0 * res[c];
    }
}

// ---------------- launch ----------------
extern "C" void kernel_launch(void* const* d_in, const int* in_sizes, int n_in,
                              void* d_out, int out_size) {
    (void)in_sizes; (void)n_in; (void)out_size;
    const float* v1f   = (const float*)d_in[0];
    const float* v2f   = (const float*)d_in[1];
    const float* v1fu  = (const float*)d_in[2];
    const float* v2fu  = (const float*)d_in[3];
    const float* Wl1   = (const float*)d_in[4];
    const float* bl1   = (const float*)d_in[5];
    const float* Wr1   = (const float*)d_in[6];
    const float* br1   = (const float*)d_in[7];
    const float* att1  = (const float*)d_in[8];
    const float* bias1 = (const float*)d_in[9];
    const float* Wl2   = (const float*)d_in[10];
    const float* bl2   = (const float*)d_in[11];
    const float* Wr2   = (const float*)d_in[12];
    const float* br2   = (const float*)d_in[13];
    const float* att2  = (const float*)d_in[14];
    const float* bias2 = (const float*)d_in[15];
    const float* Wout  = (const float*)d_in[16];
    const float* bout  = (const float*)d_in[17];
    const float* ln_g  = (const float*)d_in[18];
    const float* ln_b  = (const float*)d_in[19];
    const float* rw    = (const float*)d_in[20];
    float* out = (float*)d_out;

    float *xl1, *xr1, *o1, *xl2, *xr2, *o2, *sbuf;
    cudaGetSymbolAddress((void**)&xl1, g_xl1);
    cudaGetSymbolAddress((void**)&xr1, g_xr1);
    cudaGetSymbolAddress((void**)&o1,  g_o1);
    cudaGetSymbolAddress((void**)&xl2, g_xl2);
    cudaGetSymbolAddress((void**)&xr2, g_xr2);
    cudaGetSymbolAddress((void**)&o2,  g_o2);
    cudaGetSymbolAddress((void**)&sbuf, g_s);

    // ---- GAT layer 1 linear (reads the 4 inputs directly): split-K=2 -> 256 CTAs
    {
        dim3 grid(HD1 / 64, NN / 128, 4);
        gemm_pipe<<<grid, 256>>>(nullptr, v1f, v2f, v1fu, v2fu, Wl1, Wr1,
                                 NN, FDIM, HD1, 2, 1);
    }
    reduce_al1<<<NN, 256>>>(bl1, br1, att1);

    // ---- GAT layer 1 attention
    {
        dim3 grid(NN / 64, NN / 32, NH);
        gat_scores<HIDD><<<grid, 256>>>(xl1, xr1, att1, sbuf);
    }
    gat_softmax<<<NH * NN / 8, 256>>>(sbuf);
    {
        dim3 grid(HIDD / 64, NN / 64, NH);
        gat_agg<HIDD, 1><<<grid, 256>>>(sbuf, xl1, bias1, o1);
    }

    // ---- GAT layer 2 linear: split-K=4 -> 256 CTAs
    {
        dim3 grid(HD2 / 64, NN / 128, 8);
        gemm_pipe<<<grid, 256>>>(o1, nullptr, nullptr, nullptr, nullptr, Wl2, Wr2,
                                 NN, HD1, HD2, 4, 0);
    }
    reduce_al2<<<NN, 256>>>(bl2, br2, att2);

    // ---- GAT layer 2 attention
    {
        dim3 grid(NN / 64, NN / 32, NH);
        gat_scores<DD2><<<grid, 256>>>(xl2, xr2, att2, sbuf);
    }
    gat_softmax<<<NH * NN / 8, 256>>>(sbuf);
    {
        dim3 grid(DD2 / 64, NN / 64, NH);
        gat_agg<DD2, 0><<<grid, 256>>>(sbuf, xl2, bias2, o2);
    }

    // ---- Output projection rows 0..127: split-K=16 -> 256 CTAs
    {
        dim3 grid(FDIM / 64, 1, 16);
        gemm_pipe<<<grid, 256>>>(o2, nullptr, nullptr, nullptr, nullptr, Wout, Wout,
                                 128, FDIM, FDIM, 16, 0);
    }
    ln_residual<<<128, 256>>>(bout, ln_g, ln_b, rw, v1f, v2f, out);
}

// round 13
// speedup vs baseline: 1.0007x; 1.0007x over previous
#include <cuda_runtime.h>
#include <math.h>

#define NN   256      // total graph nodes
#define FDIM 1024
#define HIDD 512
#define NH   4
#define DD2  256
#define HD1  2048     // NH*HIDD
#define HD2  1024     // NH*DD2

typedef unsigned long long ull;

// ---- device scratch (no allocations allowed) ----
__device__ float g_xl1[NN * HD1];
__device__ float g_xr1[NN * HD1];
__device__ float g_o1 [NN * HD1];
__device__ float g_xl2[NN * HD2];
__device__ float g_xr2[NN * HD2];
__device__ float g_o2 [NN * HD2];
__device__ float g_s  [NH * NN * NN];   // RAW attention scores (softmax in agg)
__device__ float g_al [NH * NN];        // att . xl per (head, node)
__device__ float g_part[1 << 21];       // 8 MB split-K partials

// ---- packed f32x2 helpers (PTX-only path; ptxas never emits these) ----
__device__ __forceinline__ ull dupf(float x) {
    ull r;
    asm("mov.b64 %0, {%1, %1};" : "=l"(r) : "f"(x));
    return r;
}
__device__ __forceinline__ void fma2(ull& acc, ull a, ull b) {
    asm("fma.rn.f32x2 %0, %1, %2, %0;" : "+l"(acc) : "l"(a), "l"(b));
}
__device__ __forceinline__ float2 unpk(ull v) {
    float2 r;
    asm("mov.b64 {%0, %1}, %2;" : "=f"(r.x), "=f"(r.y) : "l"(v));
    return r;
}

// ------- pipelined fp32 GEMM, 128x64 tile, BK=16, split-K, dual-GEMM, FFMA2 -----
__global__ __launch_bounds__(256)
void gemm_pipe(const float* __restrict__ A,
               const float* __restrict__ I0, const float* __restrict__ I1,
               const float* __restrict__ I2, const float* __restrict__ I3,
               const float* __restrict__ W0, const float* __restrict__ W1,
               int M, int K, int N, int splitk, int fromInputs) {
    const int z = blockIdx.z;
    const int g = z / splitk;
    const int s = z % splitk;
    const float* W = g ? W1 : W0;
    const int kspan = K / splitk;
    const int kbeg  = s * kspan;
    const int nIters = kspan / 16;

    __shared__ __align__(16) float As[2][16][132];
    __shared__ __align__(16) float Ws[2][16][64];

    const int brow = blockIdx.y * 128;
    const int bcol = blockIdx.x * 64;
    const int tid  = threadIdx.x;
    const int tx   = tid & 15;        // 4 cols at tx*4
    const int ty   = tid >> 4;        // 8 rows at ty*8

    const int am0 = tid >> 2;                 // 0..63
    const int ak0 = (tid & 3) * 4;            // 0,4,8,12
    const int am1 = am0 + 64;
    const int wk = tid >> 4;
    const int wn = (tid & 15) * 4;

    const int r0 = brow + am0, r1 = brow + am1;
    const float* Ap0;
    const float* Ap1;
    if (fromInputs) {
        const float* b0 = (r0 < 64) ? I0 : (r0 < 128) ? I1 : (r0 < 192) ? I2 : I3;
        const float* b1 = (r1 < 64) ? I0 : (r1 < 128) ? I1 : (r1 < 192) ? I2 : I3;
        Ap0 = b0 + (size_t)(r0 & 63) * K + kbeg + ak0;
        Ap1 = b1 + (size_t)(r1 & 63) * K + kbeg + ak0;
    } else {
        Ap0 = A + (size_t)r0 * K + kbeg + ak0;
        Ap1 = A + (size_t)r1 * K + kbeg + ak0;
    }
    const float* Wp = W + (size_t)(kbeg + wk) * N + bcol + wn;

    ull acc[4][4];   // [i-pair][j]
#pragma unroll
    for (int i = 0; i < 4; i++)
#pragma unroll
        for (int j = 0; j < 4; j++) acc[i][j] = 0ull;

    {
        float4 ra0 = *reinterpret_cast<const float4*>(Ap0);
        float4 ra1 = *reinterpret_cast<const float4*>(Ap1);
        float4 rw  = *reinterpret_cast<const float4*>(Wp);
        As[0][ak0 + 0][am0] = ra0.x;
        As[0][ak0 + 1][am0] = ra0.y;
        As[0][ak0 + 2][am0] = ra0.z;
        As[0][ak0 + 3][am0] = ra0.w;
        As[0][ak0 + 0][am1] = ra1.x;
        As[0][ak0 + 1][am1] = ra1.y;
        As[0][ak0 + 2][am1] = ra1.z;
        As[0][ak0 + 3][am1] = ra1.w;
        *reinterpret_cast<float4*>(&Ws[0][wk][wn]) = rw;
    }
    __syncthreads();

    int buf = 0;
    for (int it = 0; it < nIters; it++) {
        const bool has_next = (it + 1) < nIters;
        float4 ra0, ra1, rw;
        if (has_next) {
            const int ko = (it + 1) * 16;
            ra0 = *reinterpret_cast<const float4*>(Ap0 + ko);
            ra1 = *reinterpret_cast<const float4*>(Ap1 + ko);
            rw  = *reinterpret_cast<const float4*>(Wp + (size_t)ko * N);
        }
#pragma unroll
        for (int kk = 0; kk < 16; kk++) {
            ulonglong2 aP01 = *reinterpret_cast<const ulonglong2*>(&As[buf][kk][ty * 8]);
            ulonglong2 aP23 = *reinterpret_cast<const ulonglong2*>(&As[buf][kk][ty * 8 + 4]);
            float4 wv = *reinterpret_cast<const float4*>(&Ws[buf][kk][tx * 4]);
            ull w0 = dupf(wv.x);
            ull w1 = dupf(wv.y);
            ull w2 = dupf(wv.z);
            ull w3 = dupf(wv.w);
            fma2(acc[0][0], aP01.x, w0); fma2(acc[0][1], aP01.x, w1);
            fma2(acc[0][2], aP01.x, w2); fma2(acc[0][3], aP01.x, w3);
            fma2(acc[1][0], aP01.y, w0); fma2(acc[1][1], aP01.y, w1);
            fma2(acc[1][2], aP01.y, w2); fma2(acc[1][3], aP01.y, w3);
            fma2(acc[2][0], aP23.x, w0); fma2(acc[2][1], aP23.x, w1);
            fma2(acc[2][2], aP23.x, w2); fma2(acc[2][3], aP23.x, w3);
            fma2(acc[3][0], aP23.y, w0); fma2(acc[3][1], aP23.y, w1);
            fma2(acc[3][2], aP23.y, w2); fma2(acc[3][3], aP23.y, w3);
        }
        if (has_next) {
            int nb = buf ^ 1;
            As[nb][ak0 + 0][am0] = ra0.x;
            As[nb][ak0 + 1][am0] = ra0.y;
            As[nb][ak0 + 2][am0] = ra0.z;
            As[nb][ak0 + 3][am0] = ra0.w;
            As[nb][ak0 + 0][am1] = ra1.x;
            As[nb][ak0 + 1][am1] = ra1.y;
            As[nb][ak0 + 2][am1] = ra1.z;
            As[nb][ak0 + 3][am1] = ra1.w;
            *reinterpret_cast<float4*>(&Ws[nb][wk][wn]) = rw;
            __syncthreads();
            buf = nb;
        }
    }

    float* P = g_part + (size_t)z * M * N;
    const int n = bcol + tx * 4;
#pragma unroll
    for (int ip = 0; ip < 4; ip++) {
        float2 c0 = unpk(acc[ip][0]);
        float2 c1 = unpk(acc[ip][1]);
        float2 c2 = unpk(acc[ip][2]);
        float2 c3 = unpk(acc[ip][3]);
        int m0 = brow + ty * 8 + 2 * ip;
        float4 rr0; rr0.x = c0.x; rr0.y = c1.x; rr0.z = c2.x; rr0.w = c3.x;
        float4 rr1; rr1.x = c0.y; rr1.y = c1.y; rr1.z = c2.y; rr1.w = c3.y;
        *reinterpret_cast<float4*>(&P[(size_t)m0 * N + n])       = rr0;
        *reinterpret_cast<float4*>(&P[(size_t)(m0 + 1) * N + n]) = rr1;
    }
}

// ---- split-K reduce + bias + fused al = att.xl per (head, node) ----
__global__ __launch_bounds__(256)
void reduce_al1(const float* __restrict__ b0, const float* __restrict__ b1,
                const float* __restrict__ att) {
    const int n = blockIdx.x;
    const int tid = threadIdx.x;
    const int lane = tid & 31, w = tid >> 5;
    const int MN = NN * HD1;
    const size_t ro = (size_t)n * HD1;
    __shared__ float sred[8];

    float alp = 0.f;
#pragma unroll
    for (int q = 0; q < 2; q++) {
        int c = tid * 8 + q * 4;
        float4 p0 = *reinterpret_cast<const float4*>(&g_part[ro + c]);
        float4 p1 = *reinterpret_cast<const float4*>(&g_part[MN + ro + c]);
        float4 bb = *reinterpret_cast<const float4*>(&b0[c]);
        float4 v;
        v.x = p0.x + p1.x + bb.x;
        v.y = p0.y + p1.y + bb.y;
        v.z = p0.z + p1.z + bb.z;
        v.w = p0.w + p1.w + bb.w;
        *reinterpret_cast<float4*>(&g_xl1[ro + c]) = v;
        float4 at = *reinterpret_cast<const float4*>(&att[c]);
        alp = fmaf(at.x, v.x, alp);
        alp = fmaf(at.y, v.y, alp);
        alp = fmaf(at.z, v.z, alp);
        alp = fmaf(at.w, v.w, alp);

        float4 q0 = *reinterpret_cast<const float4*>(&g_part[2 * (size_t)MN + ro + c]);
        float4 q1 = *reinterpret_cast<const float4*>(&g_part[3 * (size_t)MN + ro + c]);
        float4 b2 = *reinterpret_cast<const float4*>(&b1[c]);
        float4 u;
        u.x = q0.x + q1.x + b2.x;
        u.y = q0.y + q1.y + b2.y;
        u.z = q0.z + q1.z + b2.z;
        u.w = q0.w + q1.w + b2.w;
        *reinterpret_cast<float4*>(&g_xr1[ro + c]) = u;
    }
#pragma unroll
    for (int o = 16; o; o >>= 1) alp += __shfl_xor_sync(0xffffffffu, alp, o);
    if (lane == 0) sred[w] = alp;
    __syncthreads();
    if (tid < 4) g_al[tid * NN + n] = sred[2 * tid] + sred[2 * tid + 1];
}

__global__ __launch_bounds__(256)
void reduce_al2(const float* __restrict__ b0, const float* __restrict__ b1,
                const float* __restrict__ att) {
    const int n = blockIdx.x;
    const int tid = threadIdx.x;
    const int lane = tid & 31, w = tid >> 5;
    const int MN = NN * HD2;
    const size_t ro = (size_t)n * HD2;
    __shared__ float sred[8];

    int c = tid * 4;
    float4 p0 = *reinterpret_cast<const float4*>(&g_part[ro + c]);
    float4 p1 = *reinterpret_cast<const float4*>(&g_part[(size_t)MN + ro + c]);
    float4 p2 = *reinterpret_cast<const float4*>(&g_part[2 * (size_t)MN + ro + c]);
    float4 p3 = *reinterpret_cast<const float4*>(&g_part[3 * (size_t)MN + ro + c]);
    float4 bb = *reinterpret_cast<const float4*>(&b0[c]);
    float4 v;
    v.x = p0.x + p1.x + p2.x + p3.x + bb.x;
    v.y = p0.y + p1.y + p2.y + p3.y + bb.y;
    v.z = p0.z + p1.z + p2.z + p3.z + bb.z;
    v.w = p0.w + p1.w + p2.w + p3.w + bb.w;
    *reinterpret_cast<float4*>(&g_xl2[ro + c]) = v;
    float4 at = *reinterpret_cast<const float4*>(&att[c]);
    float alp = at.x * v.x + at.y * v.y + at.z * v.z + at.w * v.w;

    float4 q0 = *reinterpret_cast<const float4*>(&g_part[4 * (size_t)MN + ro + c]);
    float4 q1 = *reinterpret_cast<const float4*>(&g_part[5 * (size_t)MN + ro + c]);
    float4 q2 = *reinterpret_cast<const float4*>(&g_part[6 * (size_t)MN + ro + c]);
    float4 q3 = *reinterpret_cast<const float4*>(&g_part[7 * (size_t)MN + ro + c]);
    float4 b2 = *reinterpret_cast<const float4*>(&b1[c]);
    float4 u;
    u.x = q0.x + q1.x + q2.x + q3.x + b2.x;
    u.y = q0.y + q1.y + q2.y + q3.y + b2.y;
    u.z = q0.z + q1.z + q2.z + q3.z + b2.z;
    u.w = q0.w + q1.w + q2.w + q3.w + b2.w;
    *reinterpret_cast<float4*>(&g_xr2[ro + c]) = u;

#pragma unroll
    for (int o = 16; o; o >>= 1) alp += __shfl_xor_sync(0xffffffffu, alp, o);
    if (lane == 0) sred[w] = alp;
    __syncthreads();
    if (tid < 4) g_al[tid * NN + n] = sred[2 * tid] + sred[2 * tid + 1];
}

// ---------------- GATv2 scores via abs identity: 32i x 64j tile ----------------
// lrelu(z,0.2) = 0.6 z + 0.4 |z|; the 0.6*ar_i term cancels in softmax.
// raw s[h,i,j] = 0.6*al[h,j] + sum_d (0.4*att[h,d])*|xr_i+xl_j|  (softmax in agg)
template <int D>
__global__ __launch_bounds__(256)
void gat_scores(const float* __restrict__ xl, const float* __restrict__ xr,
                const float* __restrict__ att, float* __restrict__ s_out) {
    const int HD = NH * D;
    const int j0 = blockIdx.x * 64;
    const int i0 = blockIdx.y * 32;
    const int h  = blockIdx.z;
    const int tid = threadIdx.x;
    const int tx = tid & 15, ty = tid >> 4;    // thread -> 2 i's (ty*2), 4 j's (tx*4)

    __shared__ __align__(16) float s_xr[64][34];   // [d][i]
    __shared__ __align__(16) float s_xl[64][68];   // [d][j]
    __shared__ float s_attf[D];

    for (int d = tid; d < D; d += 256) s_attf[d] = 0.4f * att[h * D + d];

    float acc[2][4] = {{0.f, 0.f, 0.f, 0.f}, {0.f, 0.f, 0.f, 0.f}};

    for (int d0 = 0; d0 < D; d0 += 64) {
        // xr: 32 rows x 64 d
#pragma unroll
        for (int r = 0; r < 2; r++) {
            int idx = tid + r * 256;
            int row = idx >> 4;
            int kk  = (idx & 15) * 4;
            float4 v = *reinterpret_cast<const float4*>(
                &xr[(size_t)(i0 + row) * HD + h * D + d0 + kk]);
            s_xr[kk + 0][row] = v.x;
            s_xr[kk + 1][row] = v.y;
            s_xr[kk + 2][row] = v.z;
            s_xr[kk + 3][row] = v.w;
        }
        // xl: 64 rows x 64 d
#pragma unroll
        for (int r = 0; r < 4; r++) {
            int idx = tid + r * 256;
            int row = idx >> 4;
            int kk  = (idx & 15) * 4;
            float4 v = *reinterpret_cast<const float4*>(
                &xl[(size_t)(j0 + row) * HD + h * D + d0 + kk]);
            s_xl[kk + 0][row] = v.x;
            s_xl[kk + 1][row] = v.y;
            s_xl[kk + 2][row] = v.z;
            s_xl[kk + 3][row] = v.w;
        }
        __syncthreads();
#pragma unroll 8
        for (int kk = 0; kk < 64; kk++) {
            float attv = s_attf[d0 + kk];
            float2 xrP = *reinterpret_cast<const float2*>(&s_xr[kk][ty * 2]);
            float4 xlP = *reinterpret_cast<const float4*>(&s_xl[kk][tx * 4]);
            acc[0][0] = fmaf(attv, fabsf(xrP.x + xlP.x), acc[0][0]);
            acc[0][1] = fmaf(attv, fabsf(xrP.x + xlP.y), acc[0][1]);
            acc[0][2] = fmaf(attv, fabsf(xrP.x + xlP.z), acc[0][2]);
            acc[0][3] = fmaf(attv, fabsf(xrP.x + xlP.w), acc[0][3]);
            acc[1][0] = fmaf(attv, fabsf(xrP.y + xlP.x), acc[1][0]);
            acc[1][1] = fmaf(attv, fabsf(xrP.y + xlP.y), acc[1][1]);
            acc[1][2] = fmaf(attv, fabsf(xrP.y + xlP.z), acc[1][2]);
            acc[1][3] = fmaf(attv, fabsf(xrP.y + xlP.w), acc[1][3]);
        }
        __syncthreads();
    }

    float4 alv = *reinterpret_cast<const float4*>(&g_al[h * NN + j0 + tx * 4]);
#pragma unroll
    for (int ii = 0; ii < 2; ii++) {
        int i = i0 + ty * 2 + ii;
        int jb = j0 + tx * 4;
        float4 o;
        o.x = fmaf(0.6f, alv.x, acc[ii][0]);
        o.y = fmaf(0.6f, alv.y, acc[ii][1]);
        o.z = fmaf(0.6f, alv.z, acc[ii][2]);
        o.w = fmaf(0.6f, alv.w, acc[ii][3]);
        if (i - jb >= 0 && i - jb < 4) {
            if (i == jb + 0) o.x = -INFINITY;
            if (i == jb + 1) o.y = -INFINITY;
            if (i == jb + 2) o.z = -INFINITY;
            if (i == jb + 3) o.w = -INFINITY;
        }
        *reinterpret_cast<float4*>(&s_out[((size_t)h * NN + i) * NN + jb]) = o;
    }
}

// ---- aggregation GEMM per head with FUSED softmax: 64x64 tile, 4i x 4j, FFMA2 ----
// Prepass computes per-row max and 1/sum(exp) over the CTA's 64 raw-score rows;
// the A-tile loader applies exp((s-m))*inv so the GEMM consumes softmax weights.
template <int D, int ACT>
__global__ __launch_bounds__(256)
void gat_agg(const float* __restrict__ a, const float* __restrict__ xl,
             const float* __restrict__ bias, float* __restrict__ out) {
    const int HD = NH * D;
    const int h = blockIdx.z;
    const int brow = blockIdx.y * 64;
    const int bcol = blockIdx.x * 64;
    const float* A = a + (size_t)h * NN * NN;
    const float* B = xl + h * D;

    __shared__ __align__(16) float As[2][32][68];   // k-major A (i contiguous)
    __shared__ __align__(16) float Ws[2][32][64];
    __shared__ float s_m[64], s_inv[64];

    const int tid = threadIdx.x;
    const int tx = tid & 15;          // 4 j's at tx*4
    const int ty = tid >> 4;          // 4 i's at ty*4
    const int w = tid >> 5, lane = tid & 31;

    // ---- softmax prepass: warp per row, 8 passes (rows 0..63 local)
#pragma unroll
    for (int p = 0; p < 8; p++) {
        int r = p * 8 + w;
        const float* rowp = A + (size_t)(brow + r) * NN;
        float4 v0 = *reinterpret_cast<const float4*>(&rowp[lane * 8]);
        float4 v1 = *reinterpret_cast<const float4*>(&rowp[lane * 8 + 4]);
        float m = fmaxf(fmaxf(fmaxf(v0.x, v0.y), fmaxf(v0.z, v0.w)),
                        fmaxf(fmaxf(v1.x, v1.y), fmaxf(v1.z, v1.w)));
#pragma unroll
        for (int o = 16; o; o >>= 1) m = fmaxf(m, __shfl_xor_sync(0xffffffffu, m, o));
        float ss = __expf(v0.x - m) + __expf(v0.y - m) + __expf(v0.z - m) + __expf(v0.w - m)
                 + __expf(v1.x - m) + __expf(v1.y - m) + __expf(v1.z - m) + __expf(v1.w - m);
#pragma unroll
        for (int o = 16; o; o >>= 1) ss += __shfl_xor_sync(0xffffffffu, ss, o);
        if (lane == 0) { s_m[r] = m; s_inv[r] = 1.f / ss; }
    }
    __syncthreads();

    const int aIdx0 = tid * 4;                // 0..1020
    const int am0 = aIdx0 >> 5, ak0 = aIdx0 & 31;   // rows 0..31
    const int am1 = am0 + 32;                        // rows 32..63
    const int wk0 = tid >> 4;                 // rows 0..15
    const int wk1 = wk0 + 16;                 // rows 16..31
    const int wn  = (tid & 15) * 4;

    const float m0 = s_m[am0], i0v = s_inv[am0];
    const float m1 = s_m[am1], i1v = s_inv[am1];

    const float* Ap0 = A + (size_t)(brow + am0) * NN + ak0;
    const float* Ap1 = A + (size_t)(brow + am1) * NN + ak0;
    const float* Bp0 = B + (size_t)wk0 * HD + bcol + wn;
    const float* Bp1 = B + (size_t)wk1 * HD + bcol + wn;

    ull acc[4][2];   // [i][j-pair]
#pragma unroll
    for (int i = 0; i < 4; i++) { acc[i][0] = 0ull; acc[i][1] = 0ull; }

    {
        float4 ra0 = *reinterpret_cast<const float4*>(Ap0);
        float4 ra1 = *reinterpret_cast<const float4*>(Ap1);
        float4 rw0 = *reinterpret_cast<const float4*>(Bp0);
        float4 rw1 = *reinterpret_cast<const float4*>(Bp1);
        As[0][ak0 + 0][am0] = __expf(ra0.x - m0) * i0v;
        As[0][ak0 + 1][am0] = __expf(ra0.y - m0) * i0v;
        As[0][ak0 + 2][am0] = __expf(ra0.z - m0) * i0v;
        As[0][ak0 + 3][am0] = __expf(ra0.w - m0) * i0v;
        As[0][ak0 + 0][am1] = __expf(ra1.x - m1) * i1v;
        As[0][ak0 + 1][am1] = __expf(ra1.y - m1) * i1v;
        As[0][ak0 + 2][am1] = __expf(ra1.z - m1) * i1v;
        As[0][ak0 + 3][am1] = __expf(ra1.w - m1) * i1v;
        *reinterpret_cast<float4*>(&Ws[0][wk0][wn]) = rw0;
        *reinterpret_cast<float4*>(&Ws[0][wk1][wn]) = rw1;
    }
    __syncthreads();

    int buf = 0;
    const int nIters = NN / 32;   // 8
    for (int it = 0; it < nIters; it++) {
        const bool has_next = (it + 1) < nIters;
        float4 ra0, ra1, rw0, rw1;
        if (has_next) {
            const int ko = (it + 1) * 32;
            ra0 = *reinterpret_cast<const float4*>(Ap0 + ko);
            ra1 = *reinterpret_cast<const float4*>(Ap1 + ko);
            rw0 = *reinterpret_cast<const float4*>(Bp0 + (size_t)ko * HD);
            rw1 = *reinterpret_cast<const float4*>(Bp1 + (size_t)ko * HD);
        }
#pragma unroll
        for (int kk = 0; kk < 32; kk++) {
            float4 av = *reinterpret_cast<const float4*>(&As[buf][kk][ty * 4]);
            ulonglong2 wP = *reinterpret_cast<const ulonglong2*>(&Ws[buf][kk][tx * 4]);
            ull a0 = dupf(av.x);
            ull a1 = dupf(av.y);
            ull a2 = dupf(av.z);
            ull a3 = dupf(av.w);
            fma2(acc[0][0], a0, wP.x); fma2(acc[0][1], a0, wP.y);
            fma2(acc[1][0], a1, wP.x); fma2(acc[1][1], a1, wP.y);
            fma2(acc[2][0], a2, wP.x); fma2(acc[2][1], a2, wP.y);
            fma2(acc[3][0], a3, wP.x); fma2(acc[3][1], a3, wP.y);
        }
        if (has_next) {
            int nb = buf ^ 1;
            As[nb][ak0 + 0][am0] = __expf(ra0.x - m0) * i0v;
            As[nb][ak0 + 1][am0] = __expf(ra0.y - m0) * i0v;
            As[nb][ak0 + 2][am0] = __expf(ra0.z - m0) * i0v;
            As[nb][ak0 + 3][am0] = __expf(ra0.w - m0) * i0v;
            As[nb][ak0 + 0][am1] = __expf(ra1.x - m1) * i1v;
            As[nb][ak0 + 1][am1] = __expf(ra1.y - m1) * i1v;
            As[nb][ak0 + 2][am1] = __expf(ra1.z - m1) * i1v;
            As[nb][ak0 + 3][am1] = __expf(ra1.w - m1) * i1v;
            *reinterpret_cast<float4*>(&Ws[nb][wk0][wn]) = rw0;
            *reinterpret_cast<float4*>(&Ws[nb][wk1][wn]) = rw1;
            __syncthreads();
            buf = nb;
        }
    }

    const int n = bcol + tx * 4;
    float4 bv = *reinterpret_cast<const float4*>(&bias[h * D + n]);
#pragma unroll
    for (int i = 0; i < 4; i++) {
        int m = brow + ty * 4 + i;
        float2 lo = unpk(acc[i][0]);
        float2 hi = unpk(acc[i][1]);
        float4 o;
        o.x = lo.x + bv.x;
        o.y = lo.y + bv.y;
        o.z = hi.x + bv.z;
        o.w = hi.y + bv.w;
        if (ACT == 1) {
            o.x = o.x > 0.f ? o.x : expm1f(o.x);
            o.y = o.y > 0.f ? o.y : expm1f(o.y);
            o.z = o.z > 0.f ? o.z : expm1f(o.z);
            o.w = o.w > 0.f ? o.w : expm1f(o.w);
        }
        *reinterpret_cast<float4*>(&out[(size_t)m * HD + h * D + n]) = o;
    }
}

// ------- LayerNorm + ReLU + residual, rows 0..127; sums Wout's 16 split-K partials
__global__ __launch_bounds__(256)
void ln_residual(const float* __restrict__ bout,
                 const float* __restrict__ ln_g, const float* __restrict__ ln_b,
                 const float* __restrict__ rw,
                 const float* __restrict__ v1f, const float* __restrict__ v2f,
                 float* __restrict__ out) {
    const int i = blockIdx.x;
    const int tid = threadIdx.x;
    const int lane = tid & 31, warp = tid >> 5;
    const int MN = 128 * FDIM;
    __shared__ float s_red1[8], s_red2[8];
    __shared__ float s_mu, s_rstd;

    const float* res = (i < 64) ? (v1f + (size_t)i * FDIM)
                                : (v2f + (size_t)(i - 64) * FDIM);

    float yv[4];
    float sum = 0.f, sq = 0.f;
#pragma unroll
    for (int q = 0; q < 4; q++) {
        int c = tid + q * 256;
        float v = bout[c];
#pragma unroll
        for (int s = 0; s < 16; s++)
            v += g_part[(size_t)s * MN + i * FDIM + c];
        yv[q] = v;
        sum += v; sq += v * v;
    }
#pragma unroll
    for (int o = 16; o; o >>= 1) {
        sum += __shfl_xor_sync(0xffffffffu, sum, o);
        sq  += __shfl_xor_sync(0xffffffffu, sq,  o);
    }
    if (lane == 0) { s_red1[warp] = sum; s_red2[warp] = sq; }
    __syncthreads();
    if (tid == 0) {
        float ts = 0.f, tq = 0.f;
        for (int w = 0; w < 8; w++) { ts += s_red1[w]; tq += s_red2[w]; }
        float mu = ts / FDIM;
        float var = tq / FDIM - mu * mu;
        s_mu = mu;
        s_rstd = rsqrtf(var + 1e-5f);
    }
    __syncthreads();
    float mu = s_mu, rstd = s_rstd, w0 = rw[0];
#pragma unroll
    for (int q = 0; q < 4; q++) {
        int c = tid + q * 256;
        float v = (yv[q] - mu) * rstd * ln_g[c] + ln_b[c];
        v = fmaxf(v, 0.f);
        out[i * FDIM + c] = v + w0 * res[c];
    }
}

// ---------------- launch ----------------
extern "C" void kernel_launch(void* const* d_in, const int* in_sizes, int n_in,
                              void* d_out, int out_size) {
    (void)in_sizes; (void)n_in; (void)out_size;
    const float* v1f   = (const float*)d_in[0];
    const float* v2f   = (const float*)d_in[1];
    const float* v1fu  = (const float*)d_in[2];
    const float* v2fu  = (const float*)d_in[3];
    const float* Wl1   = (const float*)d_in[4];
    const float* bl1   = (const float*)d_in[5];
    const float* Wr1   = (const float*)d_in[6];
    const float* br1   = (const float*)d_in[7];
    const float* att1  = (const float*)d_in[8];
    const float* bias1 = (const float*)d_in[9];
    const float* Wl2   = (const float*)d_in[10];
    const float* bl2   = (const float*)d_in[11];
    const float* Wr2   = (const float*)d_in[12];
    const float* br2   = (const float*)d_in[13];
    const float* att2  = (const float*)d_in[14];
    const float* bias2 = (const float*)d_in[15];
    const float* Wout  = (const float*)d_in[16];
    const float* bout  = (const float*)d_in[17];
    const float* ln_g  = (const float*)d_in[18];
    const float* ln_b  = (const float*)d_in[19];
    const float* rw    = (const float*)d_in[20];
    float* out = (float*)d_out;

    float *xl1, *xr1, *o1, *xl2, *xr2, *o2, *sbuf;
    cudaGetSymbolAddress((void**)&xl1, g_xl1);
    cudaGetSymbolAddress((void**)&xr1, g_xr1);
    cudaGetSymbolAddress((void**)&o1,  g_o1);
    cudaGetSymbolAddress((void**)&xl2, g_xl2);
    cudaGetSymbolAddress((void**)&xr2, g_xr2);
    cudaGetSymbolAddress((void**)&o2,  g_o2);
    cudaGetSymbolAddress((void**)&sbuf, g_s);

    // ---- GAT layer 1 linear (reads the 4 inputs directly): split-K=2 -> 256 CTAs
    {
        dim3 grid(HD1 / 64, NN / 128, 4);
        gemm_pipe<<<grid, 256>>>(nullptr, v1f, v2f, v1fu, v2fu, Wl1, Wr1,
                                 NN, FDIM, HD1, 2, 1);
    }
    reduce_al1<<<NN, 256>>>(bl1, br1, att1);

    // ---- GAT layer 1 attention (softmax fused into agg)
    {
        dim3 grid(NN / 64, NN / 32, NH);
        gat_scores<HIDD><<<grid, 256>>>(xl1, xr1, att1, sbuf);
    }
    {
        dim3 grid(HIDD / 64, NN / 64, NH);
        gat_agg<HIDD, 1><<<grid, 256>>>(sbuf, xl1, bias1, o1);
    }

    // ---- GAT layer 2 linear: split-K=4 -> 256 CTAs
    {
        dim3 grid(HD2 / 64, NN / 128, 8);
        gemm_pipe<<<grid, 256>>>(o1, nullptr, nullptr, nullptr, nullptr, Wl2, Wr2,
                                 NN, HD1, HD2, 4, 0);
    }
    reduce_al2<<<NN, 256>>>(bl2, br2, att2);

    // ---- GAT layer 2 attention (softmax fused into agg)
    {
        dim3 grid(NN / 64, NN / 32, NH);
        gat_scores<DD2><<<grid, 256>>>(xl2, xr2, att2, sbuf);
    }
    {
        dim3 grid(DD2 / 64, NN / 64, NH);
        gat_agg<DD2, 0><<<grid, 256>>>(sbuf, xl2, bias2, o2);
    }

    // ---- Output projection rows 0..127: split-K=16 -> 256 CTAs
    {
        dim3 grid(FDIM / 64, 1, 16);
        gemm_pipe<<<grid, 256>>>(o2, nullptr, nullptr, nullptr, nullptr, Wout, Wout,
                                 128, FDIM, FDIM, 16, 0);
    }
    ln_residual<<<128, 256>>>(bout, ln_g, ln_b, rw, v1f, v2f, out);
}

// round 14
// speedup vs baseline: 1.0247x; 1.0240x over previous
#include <cuda_runtime.h>
#include <math.h>

#define NN   256      // total graph nodes
#define FDIM 1024
#define HIDD 512
#define NH   4
#define DD2  256
#define HD1  2048     // NH*HIDD
#define HD2  1024     // NH*DD2

typedef unsigned long long ull;

// ---- device scratch (no allocations allowed) ----
__device__ float g_xl1[NN * HD1];
__device__ float g_xr1[NN * HD1];
__device__ float g_o1 [NN * HD1];
__device__ float g_xl2[NN * HD2];
__device__ float g_xr2[NN * HD2];
__device__ float g_o2 [NN * HD2];
__device__ float g_s  [NH * NN * NN];   // attention scores / weights
__device__ float g_al [NH * NN];        // att . xl per (head, node)
__device__ float g_part[1 << 21];       // 8 MB split-K partials

// ---- packed f32x2 helpers (PTX-only path; ptxas never emits these) ----
__device__ __forceinline__ ull dupf(float x) {
    ull r;
    asm("mov.b64 %0, {%1, %1};" : "=l"(r) : "f"(x));
    return r;
}
__device__ __forceinline__ void fma2(ull& acc, ull a, ull b) {
    asm("fma.rn.f32x2 %0, %1, %2, %0;" : "+l"(acc) : "l"(a), "l"(b));
}
__device__ __forceinline__ float2 unpk(ull v) {
    float2 r;
    asm("mov.b64 {%0, %1}, %2;" : "=f"(r.x), "=f"(r.y) : "l"(v));
    return r;
}

// ------- pipelined fp32 GEMM, 128x64 tile, BK=16, split-K, dual-GEMM, FFMA2 -----
__global__ __launch_bounds__(256)
void gemm_pipe(const float* __restrict__ A,
               const float* __restrict__ I0, const float* __restrict__ I1,
               const float* __restrict__ I2, const float* __restrict__ I3,
               const float* __restrict__ W0, const float* __restrict__ W1,
               int M, int K, int N, int splitk, int fromInputs) {
    const int z = blockIdx.z;
    const int g = z / splitk;
    const int s = z % splitk;
    const float* W = g ? W1 : W0;
    const int kspan = K / splitk;
    const int kbeg  = s * kspan;
    const int nIters = kspan / 16;

    __shared__ __align__(16) float As[2][16][132];
    __shared__ __align__(16) float Ws[2][16][64];

    const int brow = blockIdx.y * 128;
    const int bcol = blockIdx.x * 64;
    const int tid  = threadIdx.x;
    const int tx   = tid & 15;        // 4 cols at tx*4
    const int ty   = tid >> 4;        // 8 rows at ty*8

    const int am0 = tid >> 2;                 // 0..63
    const int ak0 = (tid & 3) * 4;            // 0,4,8,12
    const int am1 = am0 + 64;
    const int wk = tid >> 4;
    const int wn = (tid & 15) * 4;

    const int r0 = brow + am0, r1 = brow + am1;
    const float* Ap0;
    const float* Ap1;
    if (fromInputs) {
        const float* b0 = (r0 < 64) ? I0 : (r0 < 128) ? I1 : (r0 < 192) ? I2 : I3;
        const float* b1 = (r1 < 64) ? I0 : (r1 < 128) ? I1 : (r1 < 192) ? I2 : I3;
        Ap0 = b0 + (size_t)(r0 & 63) * K + kbeg + ak0;
        Ap1 = b1 + (size_t)(r1 & 63) * K + kbeg + ak0;
    } else {
        Ap0 = A + (size_t)r0 * K + kbeg + ak0;
        Ap1 = A + (size_t)r1 * K + kbeg + ak0;
    }
    const float* Wp = W + (size_t)(kbeg + wk) * N + bcol + wn;

    ull acc[4][4];   // [i-pair][j]
#pragma unroll
    for (int i = 0; i < 4; i++)
#pragma unroll
        for (int j = 0; j < 4; j++) acc[i][j] = 0ull;

    {
        float4 ra0 = *reinterpret_cast<const float4*>(Ap0);
        float4 ra1 = *reinterpret_cast<const float4*>(Ap1);
        float4 rw  = *reinterpret_cast<const float4*>(Wp);
        As[0][ak0 + 0][am0] = ra0.x;
        As[0][ak0 + 1][am0] = ra0.y;
        As[0][ak0 + 2][am0] = ra0.z;
        As[0][ak0 + 3][am0] = ra0.w;
        As[0][ak0 + 0][am1] = ra1.x;
        As[0][ak0 + 1][am1] = ra1.y;
        As[0][ak0 + 2][am1] = ra1.z;
        As[0][ak0 + 3][am1] = ra1.w;
        *reinterpret_cast<float4*>(&Ws[0][wk][wn]) = rw;
    }
    __syncthreads();

    int buf = 0;
    for (int it = 0; it < nIters; it++) {
        const bool has_next = (it + 1) < nIters;
        float4 ra0, ra1, rw;
        if (has_next) {
            const int ko = (it + 1) * 16;
            ra0 = *reinterpret_cast<const float4*>(Ap0 + ko);
            ra1 = *reinterpret_cast<const float4*>(Ap1 + ko);
            rw  = *reinterpret_cast<const float4*>(Wp + (size_t)ko * N);
        }
#pragma unroll
        for (int kk = 0; kk < 16; kk++) {
            ulonglong2 aP01 = *reinterpret_cast<const ulonglong2*>(&As[buf][kk][ty * 8]);
            ulonglong2 aP23 = *reinterpret_cast<const ulonglong2*>(&As[buf][kk][ty * 8 + 4]);
            float4 wv = *reinterpret_cast<const float4*>(&Ws[buf][kk][tx * 4]);
            ull w0 = dupf(wv.x);
            ull w1 = dupf(wv.y);
            ull w2 = dupf(wv.z);
            ull w3 = dupf(wv.w);
            fma2(acc[0][0], aP01.x, w0); fma2(acc[0][1], aP01.x, w1);
            fma2(acc[0][2], aP01.x, w2); fma2(acc[0][3], aP01.x, w3);
            fma2(acc[1][0], aP01.y, w0); fma2(acc[1][1], aP01.y, w1);
            fma2(acc[1][2], aP01.y, w2); fma2(acc[1][3], aP01.y, w3);
            fma2(acc[2][0], aP23.x, w0); fma2(acc[2][1], aP23.x, w1);
            fma2(acc[2][2], aP23.x, w2); fma2(acc[2][3], aP23.x, w3);
            fma2(acc[3][0], aP23.y, w0); fma2(acc[3][1], aP23.y, w1);
            fma2(acc[3][2], aP23.y, w2); fma2(acc[3][3], aP23.y, w3);
        }
        if (has_next) {
            int nb = buf ^ 1;
            As[nb][ak0 + 0][am0] = ra0.x;
            As[nb][ak0 + 1][am0] = ra0.y;
            As[nb][ak0 + 2][am0] = ra0.z;
            As[nb][ak0 + 3][am0] = ra0.w;
            As[nb][ak0 + 0][am1] = ra1.x;
            As[nb][ak0 + 1][am1] = ra1.y;
            As[nb][ak0 + 2][am1] = ra1.z;
            As[nb][ak0 + 3][am1] = ra1.w;
            *reinterpret_cast<float4*>(&Ws[nb][wk][wn]) = rw;
            __syncthreads();
            buf = nb;
        }
    }

    float* P = g_part + (size_t)z * M * N;
    const int n = bcol + tx * 4;
#pragma unroll
    for (int ip = 0; ip < 4; ip++) {
        float2 c0 = unpk(acc[ip][0]);
        float2 c1 = unpk(acc[ip][1]);
        float2 c2 = unpk(acc[ip][2]);
        float2 c3 = unpk(acc[ip][3]);
        int m0 = brow + ty * 8 + 2 * ip;
        float4 rr0; rr0.x = c0.x; rr0.y = c1.x; rr0.z = c2.x; rr0.w = c3.x;
        float4 rr1; rr1.x = c0.y; rr1.y = c1.y; rr1.z = c2.y; rr1.w = c3.y;
        *reinterpret_cast<float4*>(&P[(size_t)m0 * N + n])       = rr0;
        *reinterpret_cast<float4*>(&P[(size_t)(m0 + 1) * N + n]) = rr1;
    }
}

// ---- split-K reduce + bias + fused al = att.xl per (head, node) ----
__global__ __launch_bounds__(256)
void reduce_al1(const float* __restrict__ b0, const float* __restrict__ b1,
                const float* __restrict__ att) {
    const int n = blockIdx.x;
    const int tid = threadIdx.x;
    const int lane = tid & 31, w = tid >> 5;
    const int MN = NN * HD1;
    const size_t ro = (size_t)n * HD1;
    __shared__ float sred[8];

    float alp = 0.f;
#pragma unroll
    for (int q = 0; q < 2; q++) {
        int c = tid * 8 + q * 4;
        float4 p0 = *reinterpret_cast<const float4*>(&g_part[ro + c]);
        float4 p1 = *reinterpret_cast<const float4*>(&g_part[MN + ro + c]);
        float4 bb = *reinterpret_cast<const float4*>(&b0[c]);
        float4 v;
        v.x = p0.x + p1.x + bb.x;
        v.y = p0.y + p1.y + bb.y;
        v.z = p0.z + p1.z + bb.z;
        v.w = p0.w + p1.w + bb.w;
        *reinterpret_cast<float4*>(&g_xl1[ro + c]) = v;
        float4 at = *reinterpret_cast<const float4*>(&att[c]);
        alp = fmaf(at.x, v.x, alp);
        alp = fmaf(at.y, v.y, alp);
        alp = fmaf(at.z, v.z, alp);
        alp = fmaf(at.w, v.w, alp);

        float4 q0 = *reinterpret_cast<const float4*>(&g_part[2 * (size_t)MN + ro + c]);
        float4 q1 = *reinterpret_cast<const float4*>(&g_part[3 * (size_t)MN + ro + c]);
        float4 b2 = *reinterpret_cast<const float4*>(&b1[c]);
        float4 u;
        u.x = q0.x + q1.x + b2.x;
        u.y = q0.y + q1.y + b2.y;
        u.z = q0.z + q1.z + b2.z;
        u.w = q0.w + q1.w + b2.w;
        *reinterpret_cast<float4*>(&g_xr1[ro + c]) = u;
    }
#pragma unroll
    for (int o = 16; o; o >>= 1) alp += __shfl_xor_sync(0xffffffffu, alp, o);
    if (lane == 0) sred[w] = alp;
    __syncthreads();
    if (tid < 4) g_al[tid * NN + n] = sred[2 * tid] + sred[2 * tid + 1];
}

__global__ __launch_bounds__(256)
void reduce_al2(const float* __restrict__ b0, const float* __restrict__ b1,
                const float* __restrict__ att) {
    const int n = blockIdx.x;
    const int tid = threadIdx.x;
    const int lane = tid & 31, w = tid >> 5;
    const int MN = NN * HD2;
    const size_t ro = (size_t)n * HD2;
    __shared__ float sred[8];

    int c = tid * 4;
    float4 p0 = *reinterpret_cast<const float4*>(&g_part[ro + c]);
    float4 p1 = *reinterpret_cast<const float4*>(&g_part[(size_t)MN + ro + c]);
    float4 p2 = *reinterpret_cast<const float4*>(&g_part[2 * (size_t)MN + ro + c]);
    float4 p3 = *reinterpret_cast<const float4*>(&g_part[3 * (size_t)MN + ro + c]);
    float4 bb = *reinterpret_cast<const float4*>(&b0[c]);
    float4 v;
    v.x = p0.x + p1.x + p2.x + p3.x + bb.x;
    v.y = p0.y + p1.y + p2.y + p3.y + bb.y;
    v.z = p0.z + p1.z + p2.z + p3.z + bb.z;
    v.w = p0.w + p1.w + p2.w + p3.w + bb.w;
    *reinterpret_cast<float4*>(&g_xl2[ro + c]) = v;
    float4 at = *reinterpret_cast<const float4*>(&att[c]);
    float alp = at.x * v.x + at.y * v.y + at.z * v.z + at.w * v.w;

    float4 q0 = *reinterpret_cast<const float4*>(&g_part[4 * (size_t)MN + ro + c]);
    float4 q1 = *reinterpret_cast<const float4*>(&g_part[5 * (size_t)MN + ro + c]);
    float4 q2 = *reinterpret_cast<const float4*>(&g_part[6 * (size_t)MN + ro + c]);
    float4 q3 = *reinterpret_cast<const float4*>(&g_part[7 * (size_t)MN + ro + c]);
    float4 b2 = *reinterpret_cast<const float4*>(&b1[c]);
    float4 u;
    u.x = q0.x + q1.x + q2.x + q3.x + b2.x;
    u.y = q0.y + q1.y + q2.y + q3.y + b2.y;
    u.z = q0.z + q1.z + q2.z + q3.z + b2.z;
    u.w = q0.w + q1.w + q2.w + q3.w + b2.w;
    *reinterpret_cast<float4*>(&g_xr2[ro + c]) = u;

#pragma unroll
    for (int o = 16; o; o >>= 1) alp += __shfl_xor_sync(0xffffffffu, alp, o);
    if (lane == 0) sred[w] = alp;
    __syncthreads();
    if (tid < 4) g_al[tid * NN + n] = sred[2 * tid] + sred[2 * tid + 1];
}

// ---------------- GATv2 scores via abs identity: 32i x 64j tile ----------------
// lrelu(z,0.2) = 0.6 z + 0.4 |z|; the 0.6*ar_i term cancels in softmax.
// s[h,i,j] = 0.6*al[h,j] + sum_d (0.4*att[h,d])*|xr_i+xl_j|
template <int D>
__global__ __launch_bounds__(256)
void gat_scores(const float* __restrict__ xl, const float* __restrict__ xr,
                const float* __restrict__ att, float* __restrict__ s_out) {
    const int HD = NH * D;
    const int j0 = blockIdx.x * 64;
    const int i0 = blockIdx.y * 32;
    const int h  = blockIdx.z;
    const int tid = threadIdx.x;
    const int tx = tid & 15, ty = tid >> 4;    // thread -> 2 i's (ty*2), 4 j's (tx*4)

    __shared__ __align__(16) float s_xr[64][34];   // [d][i]
    __shared__ __align__(16) float s_xl[64][68];   // [d][j]
    __shared__ float s_attf[D];

    for (int d = tid; d < D; d += 256) s_attf[d] = 0.4f * att[h * D + d];

    float acc[2][4] = {{0.f, 0.f, 0.f, 0.f}, {0.f, 0.f, 0.f, 0.f}};

    for (int d0 = 0; d0 < D; d0 += 64) {
        // xr: 32 rows x 64 d
#pragma unroll
        for (int r = 0; r < 2; r++) {
            int idx = tid + r * 256;
            int row = idx >> 4;
            int kk  = (idx & 15) * 4;
            float4 v = *reinterpret_cast<const float4*>(
                &xr[(size_t)(i0 + row) * HD + h * D + d0 + kk]);
            s_xr[kk + 0][row] = v.x;
            s_xr[kk + 1][row] = v.y;
            s_xr[kk + 2][row] = v.z;
            s_xr[kk + 3][row] = v.w;
        }
        // xl: 64 rows x 64 d
#pragma unroll
        for (int r = 0; r < 4; r++) {
            int idx = tid + r * 256;
            int row = idx >> 4;
            int kk  = (idx & 15) * 4;
            float4 v = *reinterpret_cast<const float4*>(
                &xl[(size_t)(j0 + row) * HD + h * D + d0 + kk]);
            s_xl[kk + 0][row] = v.x;
            s_xl[kk + 1][row] = v.y;
            s_xl[kk + 2][row] = v.z;
            s_xl[kk + 3][row] = v.w;
        }
        __syncthreads();
#pragma unroll 8
        for (int kk = 0; kk < 64; kk++) {
            float attv = s_attf[d0 + kk];
            float2 xrP = *reinterpret_cast<const float2*>(&s_xr[kk][ty * 2]);
            float4 xlP = *reinterpret_cast<const float4*>(&s_xl[kk][tx * 4]);
            acc[0][0] = fmaf(attv, fabsf(xrP.x + xlP.x), acc[0][0]);
            acc[0][1] = fmaf(attv, fabsf(xrP.x + xlP.y), acc[0][1]);
            acc[0][2] = fmaf(attv, fabsf(xrP.x + xlP.z), acc[0][2]);
            acc[0][3] = fmaf(attv, fabsf(xrP.x + xlP.w), acc[0][3]);
            acc[1][0] = fmaf(attv, fabsf(xrP.y + xlP.x), acc[1][0]);
            acc[1][1] = fmaf(attv, fabsf(xrP.y + xlP.y), acc[1][1]);
            acc[1][2] = fmaf(attv, fabsf(xrP.y + xlP.z), acc[1][2]);
            acc[1][3] = fmaf(attv, fabsf(xrP.y + xlP.w), acc[1][3]);
        }
        __syncthreads();
    }

    float4 alv = *reinterpret_cast<const float4*>(&g_al[h * NN + j0 + tx * 4]);
#pragma unroll
    for (int ii = 0; ii < 2; ii++) {
        int i = i0 + ty * 2 + ii;
        int jb = j0 + tx * 4;
        float4 o;
        o.x = fmaf(0.6f, alv.x, acc[ii][0]);
        o.y = fmaf(0.6f, alv.y, acc[ii][1]);
        o.z = fmaf(0.6f, alv.z, acc[ii][2]);
        o.w = fmaf(0.6f, alv.w, acc[ii][3]);
        if (i - jb >= 0 && i - jb < 4) {
            if (i == jb + 0) o.x = -INFINITY;
            if (i == jb + 1) o.y = -INFINITY;
            if (i == jb + 2) o.z = -INFINITY;
            if (i == jb + 3) o.w = -INFINITY;
        }
        *reinterpret_cast<float4*>(&s_out[((size_t)h * NN + i) * NN + jb]) = o;
    }
}

// ---------------- softmax: warp per row, 8 rows per CTA ----------------
__global__ __launch_bounds__(256)
void gat_softmax(float* __restrict__ s) {
    const int row = blockIdx.x * 8 + (threadIdx.x >> 5);
    const int lane = threadIdx.x & 31;
    float* r = s + (size_t)row * NN;

    float4 v0 = *reinterpret_cast<const float4*>(&r[lane * 8]);
    float4 v1 = *reinterpret_cast<const float4*>(&r[lane * 8 + 4]);
    float m = fmaxf(fmaxf(fmaxf(v0.x, v0.y), fmaxf(v0.z, v0.w)),
                    fmaxf(fmaxf(v1.x, v1.y), fmaxf(v1.z, v1.w)));
#pragma unroll
    for (int o = 16; o; o >>= 1) m = fmaxf(m, __shfl_xor_sync(0xffffffffu, m, o));
    v0.x = __expf(v0.x - m); v0.y = __expf(v0.y - m);
    v0.z = __expf(v0.z - m); v0.w = __expf(v0.w - m);
    v1.x = __expf(v1.x - m); v1.y = __expf(v1.y - m);
    v1.z = __expf(v1.z - m); v1.w = __expf(v1.w - m);
    float ss = v0.x + v0.y + v0.z + v0.w + v1.x + v1.y + v1.z + v1.w;
#pragma unroll
    for (int o = 16; o; o >>= 1) ss += __shfl_xor_sync(0xffffffffu, ss, o);
    float inv = 1.f / ss;
    v0.x *= inv; v0.y *= inv; v0.z *= inv; v0.w *= inv;
    v1.x *= inv; v1.y *= inv; v1.z *= inv; v1.w *= inv;
    *reinterpret_cast<float4*>(&r[lane * 8])     = v0;
    *reinterpret_cast<float4*>(&r[lane * 8 + 4]) = v1;
}

// ---- aggregation GEMM per head: 64x64 tile, 4i x 4j per thread, FFMA2 ----
template <int D, int ACT>
__global__ __launch_bounds__(256)
void gat_agg(const float* __restrict__ a, const float* __restrict__ xl,
             const float* __restrict__ bias, float* __restrict__ out) {
    const int HD = NH * D;
    const int h = blockIdx.z;
    const int brow = blockIdx.y * 64;
    const int bcol = blockIdx.x * 64;
    const float* A = a + (size_t)h * NN * NN;
    const float* B = xl + h * D;

    __shared__ __align__(16) float As[2][32][68];   // k-major A (i contiguous)
    __shared__ __align__(16) float Ws[2][32][64];

    const int tid = threadIdx.x;
    const int tx = tid & 15;          // 4 j's at tx*4
    const int ty = tid >> 4;          // 4 i's at ty*4

    const int aIdx0 = tid * 4;                // 0..1020
    const int am0 = aIdx0 >> 5, ak0 = aIdx0 & 31;   // rows 0..31
    const int am1 = am0 + 32;                        // rows 32..63
    const int wk0 = tid >> 4;                 // rows 0..15
    const int wk1 = wk0 + 16;                 // rows 16..31
    const int wn  = (tid & 15) * 4;

    const float* Ap0 = A + (size_t)(brow + am0) * NN + ak0;
    const float* Ap1 = A + (size_t)(brow + am1) * NN + ak0;
    const float* Bp0 = B + (size_t)wk0 * HD + bcol + wn;
    const float* Bp1 = B + (size_t)wk1 * HD + bcol + wn;

    ull acc[4][2];   // [i][j-pair]
#pragma unroll
    for (int i = 0; i < 4; i++) { acc[i][0] = 0ull; acc[i][1] = 0ull; }

    {
        float4 ra0 = *reinterpret_cast<const float4*>(Ap0);
        float4 ra1 = *reinterpret_cast<const float4*>(Ap1);
        float4 rw0 = *reinterpret_cast<const float4*>(Bp0);
        float4 rw1 = *reinterpret_cast<const float4*>(Bp1);
        As[0][ak0 + 0][am0] = ra0.x;
        As[0][ak0 + 1][am0] = ra0.y;
        As[0][ak0 + 2][am0] = ra0.z;
        As[0][ak0 + 3][am0] = ra0.w;
        As[0][ak0 + 0][am1] = ra1.x;
        As[0][ak0 + 1][am1] = ra1.y;
        As[0][ak0 + 2][am1] = ra1.z;
        As[0][ak0 + 3][am1] = ra1.w;
        *reinterpret_cast<float4*>(&Ws[0][wk0][wn]) = rw0;
        *reinterpret_cast<float4*>(&Ws[0][wk1][wn]) = rw1;
    }
    __syncthreads();

    int buf = 0;
    const int nIters = NN / 32;   // 8
    for (int it = 0; it < nIters; it++) {
        const bool has_next = (it + 1) < nIters;
        float4 ra0, ra1, rw0, rw1;
        if (has_next) {
            const int ko = (it + 1) * 32;
            ra0 = *reinterpret_cast<const float4*>(Ap0 + ko);
            ra1 = *reinterpret_cast<const float4*>(Ap1 + ko);
            rw0 = *reinterpret_cast<const float4*>(Bp0 + (size_t)ko * HD);
            rw1 = *reinterpret_cast<const float4*>(Bp1 + (size_t)ko * HD);
        }
#pragma unroll
        for (int kk = 0; kk < 32; kk++) {
            float4 av = *reinterpret_cast<const float4*>(&As[buf][kk][ty * 4]);
            ulonglong2 wP = *reinterpret_cast<const ulonglong2*>(&Ws[buf][kk][tx * 4]);
            ull a0 = dupf(av.x);
            ull a1 = dupf(av.y);
            ull a2 = dupf(av.z);
            ull a3 = dupf(av.w);
            fma2(acc[0][0], a0, wP.x); fma2(acc[0][1], a0, wP.y);
            fma2(acc[1][0], a1, wP.x); fma2(acc[1][1], a1, wP.y);
            fma2(acc[2][0], a2, wP.x); fma2(acc[2][1], a2, wP.y);
            fma2(acc[3][0], a3, wP.x); fma2(acc[3][1], a3, wP.y);
        }
        if (has_next) {
            int nb = buf ^ 1;
            As[nb][ak0 + 0][am0] = ra0.x;
            As[nb][ak0 + 1][am0] = ra0.y;
            As[nb][ak0 + 2][am0] = ra0.z;
            As[nb][ak0 + 3][am0] = ra0.w;
            As[nb][ak0 + 0][am1] = ra1.x;
            As[nb][ak0 + 1][am1] = ra1.y;
            As[nb][ak0 + 2][am1] = ra1.z;
            As[nb][ak0 + 3][am1] = ra1.w;
            *reinterpret_cast<float4*>(&Ws[nb][wk0][wn]) = rw0;
            *reinterpret_cast<float4*>(&Ws[nb][wk1][wn]) = rw1;
            __syncthreads();
            buf = nb;
        }
    }

    const int n = bcol + tx * 4;
    float4 bv = *reinterpret_cast<const float4*>(&bias[h * D + n]);
#pragma unroll
    for (int i = 0; i < 4; i++) {
        int m = brow + ty * 4 + i;
        float2 lo = unpk(acc[i][0]);
        float2 hi = unpk(acc[i][1]);
        float4 o;
        o.x = lo.x + bv.x;
        o.y = lo.y + bv.y;
        o.z = hi.x + bv.z;
        o.w = hi.y + bv.w;
        if (ACT == 1) {
            o.x = o.x > 0.f ? o.x : expm1f(o.x);
            o.y = o.y > 0.f ? o.y : expm1f(o.y);
            o.z = o.z > 0.f ? o.z : expm1f(o.z);
            o.w = o.w > 0.f ? o.w : expm1f(o.w);
        }
        *reinterpret_cast<float4*>(&out[(size_t)m * HD + h * D + n]) = o;
    }
}

// ------- LayerNorm + ReLU + residual, rows 0..127; sums Wout's 16 split-K partials
__global__ __launch_bounds__(256)
void ln_residual(const float* __restrict__ bout,
                 const float* __restrict__ ln_g, const float* __restrict__ ln_b,
                 const float* __restrict__ rw,
                 const float* __restrict__ v1f, const float* __restrict__ v2f,
                 float* __restrict__ out) {
    const int i = blockIdx.x;
    const int tid = threadIdx.x;
    const int lane = tid & 31, warp = tid >> 5;
    const int MN = 128 * FDIM;
    __shared__ float s_red1[8], s_red2[8];
    __shared__ float s_mu, s_rstd;

    const float* res = (i < 64) ? (v1f + (size_t)i * FDIM)
                                : (v2f + (size_t)(i - 64) * FDIM);

    float yv[4];
    float sum = 0.f, sq = 0.f;
#pragma unroll
    for (int q = 0; q < 4; q++) {
        int c = tid + q * 256;
        float v = bout[c];
#pragma unroll
        for (int s = 0; s < 16; s++)
            v += g_part[(size_t)s * MN + i * FDIM + c];
        yv[q] = v;
        sum += v; sq += v * v;
    }
#pragma unroll
    for (int o = 16; o; o >>= 1) {
        sum += __shfl_xor_sync(0xffffffffu, sum, o);
        sq  += __shfl_xor_sync(0xffffffffu, sq,  o);
    }
    if (lane == 0) { s_red1[warp] = sum; s_red2[warp] = sq; }
    __syncthreads();
    if (tid == 0) {
        float ts = 0.f, tq = 0.f;
        for (int w = 0; w < 8; w++) { ts += s_red1[w]; tq += s_red2[w]; }
        float mu = ts / FDIM;
        float var = tq / FDIM - mu * mu;
        s_mu = mu;
        s_rstd = rsqrtf(var + 1e-5f);
    }
    __syncthreads();
    float mu = s_mu, rstd = s_rstd, w0 = rw[0];
#pragma unroll
    for (int q = 0; q < 4; q++) {
        int c = tid + q * 256;
        float v = (yv[q] - mu) * rstd * ln_g[c] + ln_b[c];
        v = fmaxf(v, 0.f);
        out[i * FDIM + c] = v + w0 * res[c];
    }
}

// ---------------- launch ----------------
extern "C" void kernel_launch(void* const* d_in, const int* in_sizes, int n_in,
                              void* d_out, int out_size) {
    (void)in_sizes; (void)n_in; (void)out_size;
    const float* v1f   = (const float*)d_in[0];
    const float* v2f   = (const float*)d_in[1];
    const float* v1fu  = (const float*)d_in[2];
    const float* v2fu  = (const float*)d_in[3];
    const float* Wl1   = (const float*)d_in[4];
    const float* bl1   = (const float*)d_in[5];
    const float* Wr1   = (const float*)d_in[6];
    const float* br1   = (const float*)d_in[7];
    const float* att1  = (const float*)d_in[8];
    const float* bias1 = (const float*)d_in[9];
    const float* Wl2   = (const float*)d_in[10];
    const float* bl2   = (const float*)d_in[11];
    const float* Wr2   = (const float*)d_in[12];
    const float* br2   = (const float*)d_in[13];
    const float* att2  = (const float*)d_in[14];
    const float* bias2 = (const float*)d_in[15];
    const float* Wout  = (const float*)d_in[16];
    const float* bout  = (const float*)d_in[17];
    const float* ln_g  = (const float*)d_in[18];
    const float* ln_b  = (const float*)d_in[19];
    const float* rw    = (const float*)d_in[20];
    float* out = (float*)d_out;

    float *xl1, *xr1, *o1, *xl2, *xr2, *o2, *sbuf;
    cudaGetSymbolAddress((void**)&xl1, g_xl1);
    cudaGetSymbolAddress((void**)&xr1, g_xr1);
    cudaGetSymbolAddress((void**)&o1,  g_o1);
    cudaGetSymbolAddress((void**)&xl2, g_xl2);
    cudaGetSymbolAddress((void**)&xr2, g_xr2);
    cudaGetSymbolAddress((void**)&o2,  g_o2);
    cudaGetSymbolAddress((void**)&sbuf, g_s);

    // ---- GAT layer 1 linear (reads the 4 inputs directly): split-K=2 -> 256 CTAs
    {
        dim3 grid(HD1 / 64, NN / 128, 4);
        gemm_pipe<<<grid, 256>>>(nullptr, v1f, v2f, v1fu, v2fu, Wl1, Wr1,
                                 NN, FDIM, HD1, 2, 1);
    }
    reduce_al1<<<NN, 256>>>(bl1, br1, att1);

    // ---- GAT layer 1 attention
    {
        dim3 grid(NN / 64, NN / 32, NH);
        gat_scores<HIDD><<<grid, 256>>>(xl1, xr1, att1, sbuf);
    }
    gat_softmax<<<NH * NN / 8, 256>>>(sbuf);
    {
        dim3 grid(HIDD / 64, NN / 64, NH);
        gat_agg<HIDD, 1><<<grid, 256>>>(sbuf, xl1, bias1, o1);
    }

    // ---- GAT layer 2 linear: split-K=4 -> 256 CTAs
    {
        dim3 grid(HD2 / 64, NN / 128, 8);
        gemm_pipe<<<grid, 256>>>(o1, nullptr, nullptr, nullptr, nullptr, Wl2, Wr2,
                                 NN, HD1, HD2, 4, 0);
    }
    reduce_al2<<<NN, 256>>>(bl2, br2, att2);

    // ---- GAT layer 2 attention
    {
        dim3 grid(NN / 64, NN / 32, NH);
        gat_scores<DD2><<<grid, 256>>>(xl2, xr2, att2, sbuf);
    }
    gat_softmax<<<NH * NN / 8, 256>>>(sbuf);
    {
        dim3 grid(DD2 / 64, NN / 64, NH);
        gat_agg<DD2, 0><<<grid, 256>>>(sbuf, xl2, bias2, o2);
    }

    // ---- Output projection rows 0..127: split-K=16 -> 256 CTAs
    {
        dim3 grid(FDIM / 64, 1, 16);
        gemm_pipe<<<grid, 256>>>(o2, nullptr, nullptr, nullptr, nullptr, Wout, Wout,
                                 128, FDIM, FDIM, 16, 0);
    }
    ln_residual<<<128, 256>>>(bout, ln_g, ln_b, rw, v1f, v2f, out);
}

// round 15
// speedup vs baseline: 1.0432x; 1.0180x over previous
#include <cuda_runtime.h>
#include <math.h>

#define NN   256      // total graph nodes
#define FDIM 1024
#define HIDD 512
#define NH   4
#define DD2  256
#define HD1  2048     // NH*HIDD
#define HD2  1024     // NH*DD2

typedef unsigned long long ull;

// ---- device scratch (no allocations allowed) ----
__device__ float g_xl1[NN * HD1];
__device__ float g_xr1[NN * HD1];
__device__ float g_o1 [NN * HD1];
__device__ float g_xl2[NN * HD2];
__device__ float g_xr2[NN * HD2];
__device__ float g_o2 [NN * HD2];
__device__ float g_s  [NH * NN * NN];   // attention scores / weights
__device__ float g_al [NH * NN];        // att . xl per (head, node)
__device__ float g_part[1 << 21];       // 8 MB split-K partials

// ---- packed f32x2 helpers (PTX-only path; ptxas never emits these) ----
__device__ __forceinline__ ull dupf(float x) {
    ull r;
    asm("mov.b64 %0, {%1, %1};" : "=l"(r) : "f"(x));
    return r;
}
__device__ __forceinline__ void fma2(ull& acc, ull a, ull b) {
    asm("fma.rn.f32x2 %0, %1, %2, %0;" : "+l"(acc) : "l"(a), "l"(b));
}
__device__ __forceinline__ float2 unpk(ull v) {
    float2 r;
    asm("mov.b64 {%0, %1}, %2;" : "=f"(r.x), "=f"(r.y) : "l"(v));
    return r;
}

// ------- pipelined fp32 GEMM, 128x64 tile, BK=16, split-K, dual-GEMM, FFMA2 -----
__global__ __launch_bounds__(256)
void gemm_pipe(const float* __restrict__ A,
               const float* __restrict__ I0, const float* __restrict__ I1,
               const float* __restrict__ I2, const float* __restrict__ I3,
               const float* __restrict__ W0, const float* __restrict__ W1,
               int M, int K, int N, int splitk, int fromInputs) {
    const int z = blockIdx.z;
    const int g = z / splitk;
    const int s = z % splitk;
    const float* W = g ? W1 : W0;
    const int kspan = K / splitk;
    const int kbeg  = s * kspan;
    const int nIters = kspan / 16;

    __shared__ __align__(16) float As[2][16][132];
    __shared__ __align__(16) float Ws[2][16][64];

    const int brow = blockIdx.y * 128;
    const int bcol = blockIdx.x * 64;
    const int tid  = threadIdx.x;
    const int tx   = tid & 15;        // 4 cols at tx*4
    const int ty   = tid >> 4;        // 8 rows at ty*8

    const int am0 = tid >> 2;                 // 0..63
    const int ak0 = (tid & 3) * 4;            // 0,4,8,12
    const int am1 = am0 + 64;
    const int wk = tid >> 4;
    const int wn = (tid & 15) * 4;

    const int r0 = brow + am0, r1 = brow + am1;
    const float* Ap0;
    const float* Ap1;
    if (fromInputs) {
        const float* b0 = (r0 < 64) ? I0 : (r0 < 128) ? I1 : (r0 < 192) ? I2 : I3;
        const float* b1 = (r1 < 64) ? I0 : (r1 < 128) ? I1 : (r1 < 192) ? I2 : I3;
        Ap0 = b0 + (size_t)(r0 & 63) * K + kbeg + ak0;
        Ap1 = b1 + (size_t)(r1 & 63) * K + kbeg + ak0;
    } else {
        Ap0 = A + (size_t)r0 * K + kbeg + ak0;
        Ap1 = A + (size_t)r1 * K + kbeg + ak0;
    }
    const float* Wp = W + (size_t)(kbeg + wk) * N + bcol + wn;

    ull acc[4][4];   // [i-pair][j]
#pragma unroll
    for (int i = 0; i < 4; i++)
#pragma unroll
        for (int j = 0; j < 4; j++) acc[i][j] = 0ull;

    {
        float4 ra0 = *reinterpret_cast<const float4*>(Ap0);
        float4 ra1 = *reinterpret_cast<const float4*>(Ap1);
        float4 rw  = *reinterpret_cast<const float4*>(Wp);
        As[0][ak0 + 0][am0] = ra0.x;
        As[0][ak0 + 1][am0] = ra0.y;
        As[0][ak0 + 2][am0] = ra0.z;
        As[0][ak0 + 3][am0] = ra0.w;
        As[0][ak0 + 0][am1] = ra1.x;
        As[0][ak0 + 1][am1] = ra1.y;
        As[0][ak0 + 2][am1] = ra1.z;
        As[0][ak0 + 3][am1] = ra1.w;
        *reinterpret_cast<float4*>(&Ws[0][wk][wn]) = rw;
    }
    __syncthreads();

    int buf = 0;
    for (int it = 0; it < nIters; it++) {
        const bool has_next = (it + 1) < nIters;
        float4 ra0, ra1, rw;
        if (has_next) {
            const int ko = (it + 1) * 16;
            ra0 = *reinterpret_cast<const float4*>(Ap0 + ko);
            ra1 = *reinterpret_cast<const float4*>(Ap1 + ko);
            rw  = *reinterpret_cast<const float4*>(Wp + (size_t)ko * N);
        }
#pragma unroll
        for (int kk = 0; kk < 16; kk++) {
            ulonglong2 aP01 = *reinterpret_cast<const ulonglong2*>(&As[buf][kk][ty * 8]);
            ulonglong2 aP23 = *reinterpret_cast<const ulonglong2*>(&As[buf][kk][ty * 8 + 4]);
            float4 wv = *reinterpret_cast<const float4*>(&Ws[buf][kk][tx * 4]);
            ull w0 = dupf(wv.x);
            ull w1 = dupf(wv.y);
            ull w2 = dupf(wv.z);
            ull w3 = dupf(wv.w);
            fma2(acc[0][0], aP01.x, w0); fma2(acc[0][1], aP01.x, w1);
            fma2(acc[0][2], aP01.x, w2); fma2(acc[0][3], aP01.x, w3);
            fma2(acc[1][0], aP01.y, w0); fma2(acc[1][1], aP01.y, w1);
            fma2(acc[1][2], aP01.y, w2); fma2(acc[1][3], aP01.y, w3);
            fma2(acc[2][0], aP23.x, w0); fma2(acc[2][1], aP23.x, w1);
            fma2(acc[2][2], aP23.x, w2); fma2(acc[2][3], aP23.x, w3);
            fma2(acc[3][0], aP23.y, w0); fma2(acc[3][1], aP23.y, w1);
            fma2(acc[3][2], aP23.y, w2); fma2(acc[3][3], aP23.y, w3);
        }
        if (has_next) {
            int nb = buf ^ 1;
            As[nb][ak0 + 0][am0] = ra0.x;
            As[nb][ak0 + 1][am0] = ra0.y;
            As[nb][ak0 + 2][am0] = ra0.z;
            As[nb][ak0 + 3][am0] = ra0.w;
            As[nb][ak0 + 0][am1] = ra1.x;
            As[nb][ak0 + 1][am1] = ra1.y;
            As[nb][ak0 + 2][am1] = ra1.z;
            As[nb][ak0 + 3][am1] = ra1.w;
            *reinterpret_cast<float4*>(&Ws[nb][wk][wn]) = rw;
            __syncthreads();
            buf = nb;
        }
    }

    float* P = g_part + (size_t)z * M * N;
    const int n = bcol + tx * 4;
#pragma unroll
    for (int ip = 0; ip < 4; ip++) {
        float2 c0 = unpk(acc[ip][0]);
        float2 c1 = unpk(acc[ip][1]);
        float2 c2 = unpk(acc[ip][2]);
        float2 c3 = unpk(acc[ip][3]);
        int m0 = brow + ty * 8 + 2 * ip;
        float4 rr0; rr0.x = c0.x; rr0.y = c1.x; rr0.z = c2.x; rr0.w = c3.x;
        float4 rr1; rr1.x = c0.y; rr1.y = c1.y; rr1.z = c2.y; rr1.w = c3.y;
        *reinterpret_cast<float4*>(&P[(size_t)m0 * N + n])       = rr0;
        *reinterpret_cast<float4*>(&P[(size_t)(m0 + 1) * N + n]) = rr1;
    }
}

// ---- split-K reduce + bias + fused al = att.xl per (head, node) ----
__global__ __launch_bounds__(256)
void reduce_al1(const float* __restrict__ b0, const float* __restrict__ b1,
                const float* __restrict__ att) {
    const int n = blockIdx.x;
    const int tid = threadIdx.x;
    const int lane = tid & 31, w = tid >> 5;
    const int MN = NN * HD1;
    const size_t ro = (size_t)n * HD1;
    __shared__ float sred[8];

    float alp = 0.f;
#pragma unroll
    for (int q = 0; q < 2; q++) {
        int c = tid * 8 + q * 4;
        float4 p0 = *reinterpret_cast<const float4*>(&g_part[ro + c]);
        float4 p1 = *reinterpret_cast<const float4*>(&g_part[MN + ro + c]);
        float4 bb = *reinterpret_cast<const float4*>(&b0[c]);
        float4 v;
        v.x = p0.x + p1.x + bb.x;
        v.y = p0.y + p1.y + bb.y;
        v.z = p0.z + p1.z + bb.z;
        v.w = p0.w + p1.w + bb.w;
        *reinterpret_cast<float4*>(&g_xl1[ro + c]) = v;
        float4 at = *reinterpret_cast<const float4*>(&att[c]);
        alp = fmaf(at.x, v.x, alp);
        alp = fmaf(at.y, v.y, alp);
        alp = fmaf(at.z, v.z, alp);
        alp = fmaf(at.w, v.w, alp);

        float4 q0 = *reinterpret_cast<const float4*>(&g_part[2 * (size_t)MN + ro + c]);
        float4 q1 = *reinterpret_cast<const float4*>(&g_part[3 * (size_t)MN + ro + c]);
        float4 b2 = *reinterpret_cast<const float4*>(&b1[c]);
        float4 u;
        u.x = q0.x + q1.x + b2.x;
        u.y = q0.y + q1.y + b2.y;
        u.z = q0.z + q1.z + b2.z;
        u.w = q0.w + q1.w + b2.w;
        *reinterpret_cast<float4*>(&g_xr1[ro + c]) = u;
    }
#pragma unroll
    for (int o = 16; o; o >>= 1) alp += __shfl_xor_sync(0xffffffffu, alp, o);
    if (lane == 0) sred[w] = alp;
    __syncthreads();
    if (tid < 4) g_al[tid * NN + n] = sred[2 * tid] + sred[2 * tid + 1];
}

__global__ __launch_bounds__(256)
void reduce_al2(const float* __restrict__ b0, const float* __restrict__ b1,
                const float* __restrict__ att) {
    const int n = blockIdx.x;
    const int tid = threadIdx.x;
    const int lane = tid & 31, w = tid >> 5;
    const int MN = NN * HD2;
    const size_t ro = (size_t)n * HD2;
    __shared__ float sred[8];

    int c = tid * 4;
    float4 p0 = *reinterpret_cast<const float4*>(&g_part[ro + c]);
    float4 p1 = *reinterpret_cast<const float4*>(&g_part[(size_t)MN + ro + c]);
    float4 p2 = *reinterpret_cast<const float4*>(&g_part[2 * (size_t)MN + ro + c]);
    float4 p3 = *reinterpret_cast<const float4*>(&g_part[3 * (size_t)MN + ro + c]);
    float4 bb = *reinterpret_cast<const float4*>(&b0[c]);
    float4 v;
    v.x = p0.x + p1.x + p2.x + p3.x + bb.x;
    v.y = p0.y + p1.y + p2.y + p3.y + bb.y;
    v.z = p0.z + p1.z + p2.z + p3.z + bb.z;
    v.w = p0.w + p1.w + p2.w + p3.w + bb.w;
    *reinterpret_cast<float4*>(&g_xl2[ro + c]) = v;
    float4 at = *reinterpret_cast<const float4*>(&att[c]);
    float alp = at.x * v.x + at.y * v.y + at.z * v.z + at.w * v.w;

    float4 q0 = *reinterpret_cast<const float4*>(&g_part[4 * (size_t)MN + ro + c]);
    float4 q1 = *reinterpret_cast<const float4*>(&g_part[5 * (size_t)MN + ro + c]);
    float4 q2 = *reinterpret_cast<const float4*>(&g_part[6 * (size_t)MN + ro + c]);
    float4 q3 = *reinterpret_cast<const float4*>(&g_part[7 * (size_t)MN + ro + c]);
    float4 b2 = *reinterpret_cast<const float4*>(&b1[c]);
    float4 u;
    u.x = q0.x + q1.x + q2.x + q3.x + b2.x;
    u.y = q0.y + q1.y + q2.y + q3.y + b2.y;
    u.z = q0.z + q1.z + q2.z + q3.z + b2.z;
    u.w = q0.w + q1.w + q2.w + q3.w + b2.w;
    *reinterpret_cast<float4*>(&g_xr2[ro + c]) = u;

#pragma unroll
    for (int o = 16; o; o >>= 1) alp += __shfl_xor_sync(0xffffffffu, alp, o);
    if (lane == 0) sred[w] = alp;
    __syncthreads();
    if (tid < 4) g_al[tid * NN + n] = sred[2 * tid] + sred[2 * tid + 1];
}

// ---- GATv2 scores: 32i x 64j tile with register-prefetch pipeline ----
// lrelu(z,0.2) = 0.6 z + 0.4 |z|; the 0.6*ar_i term cancels in softmax.
// s[h,i,j] = 0.6*al[h,j] + sum_d (0.4*att[h,d])*|xr_i+xl_j|
template <int D>
__global__ __launch_bounds__(256)
void gat_scores(const float* __restrict__ xl, const float* __restrict__ xr,
                const float* __restrict__ att, float* __restrict__ s_out) {
    const int HD = NH * D;
    const int NC = D / 64;
    const int j0 = blockIdx.x * 64;
    const int i0 = blockIdx.y * 32;
    const int h  = blockIdx.z;
    const int tid = threadIdx.x;
    const int tx = tid & 15, ty = tid >> 4;    // thread -> 2 i's (ty*2), 4 j's (tx*4)

    __shared__ __align__(16) float s_xr[64][34];   // [d][i]
    __shared__ __align__(16) float s_xl[64][68];   // [d][j]
    __shared__ float s_attf[D];

    for (int d = tid; d < D; d += 256) s_attf[d] = 0.4f * att[h * D + d];

    // coalesced loader coords (16 threads per row, same mapping as before)
    const int lrow = tid >> 4;                 // 0..15
    const int lkk  = (tid & 15) * 4;           // 0..60
    const float* xr_base = xr + (size_t)(i0 + lrow) * HD + h * D + lkk;
    const float* xl_base = xl + (size_t)(j0 + lrow) * HD + h * D + lkk;

    float4 rx[2], rl[4];
    // preload chunk 0
#pragma unroll
    for (int r = 0; r < 2; r++)
        rx[r] = *reinterpret_cast<const float4*>(xr_base + (size_t)(16 * r) * HD);
#pragma unroll
    for (int r = 0; r < 4; r++)
        rl[r] = *reinterpret_cast<const float4*>(xl_base + (size_t)(16 * r) * HD);
#pragma unroll
    for (int r = 0; r < 2; r++) {
        int row = lrow + 16 * r;
        s_xr[lkk + 0][row] = rx[r].x;
        s_xr[lkk + 1][row] = rx[r].y;
        s_xr[lkk + 2][row] = rx[r].z;
        s_xr[lkk + 3][row] = rx[r].w;
    }
#pragma unroll
    for (int r = 0; r < 4; r++) {
        int row = lrow + 16 * r;
        s_xl[lkk + 0][row] = rl[r].x;
        s_xl[lkk + 1][row] = rl[r].y;
        s_xl[lkk + 2][row] = rl[r].z;
        s_xl[lkk + 3][row] = rl[r].w;
    }
    __syncthreads();

    float acc[2][4] = {{0.f, 0.f, 0.f, 0.f}, {0.f, 0.f, 0.f, 0.f}};

    for (int c = 0; c < NC; c++) {
        const bool has_next = (c + 1) < NC;
        if (has_next) {
            const int d1 = (c + 1) * 64;
#pragma unroll
            for (int r = 0; r < 2; r++)
                rx[r] = *reinterpret_cast<const float4*>(xr_base + d1 + (size_t)(16 * r) * HD);
#pragma unroll
            for (int r = 0; r < 4; r++)
                rl[r] = *reinterpret_cast<const float4*>(xl_base + d1 + (size_t)(16 * r) * HD);
        }
        const int d0 = c * 64;
#pragma unroll 8
        for (int kk = 0; kk < 64; kk++) {
            float attv = s_attf[d0 + kk];
            float2 xrP = *reinterpret_cast<const float2*>(&s_xr[kk][ty * 2]);
            float4 xlP = *reinterpret_cast<const float4*>(&s_xl[kk][tx * 4]);
            acc[0][0] = fmaf(attv, fabsf(xrP.x + xlP.x), acc[0][0]);
            acc[0][1] = fmaf(attv, fabsf(xrP.x + xlP.y), acc[0][1]);
            acc[0][2] = fmaf(attv, fabsf(xrP.x + xlP.z), acc[0][2]);
            acc[0][3] = fmaf(attv, fabsf(xrP.x + xlP.w), acc[0][3]);
            acc[1][0] = fmaf(attv, fabsf(xrP.y + xlP.x), acc[1][0]);
            acc[1][1] = fmaf(attv, fabsf(xrP.y + xlP.y), acc[1][1]);
            acc[1][2] = fmaf(attv, fabsf(xrP.y + xlP.z), acc[1][2]);
            acc[1][3] = fmaf(attv, fabsf(xrP.y + xlP.w), acc[1][3]);
        }
        if (has_next) {
            __syncthreads();
#pragma unroll
            for (int r = 0; r < 2; r++) {
                int row = lrow + 16 * r;
                s_xr[lkk + 0][row] = rx[r].x;
                s_xr[lkk + 1][row] = rx[r].y;
                s_xr[lkk + 2][row] = rx[r].z;
                s_xr[lkk + 3][row] = rx[r].w;
            }
#pragma unroll
            for (int r = 0; r < 4; r++) {
                int row = lrow + 16 * r;
                s_xl[lkk + 0][row] = rl[r].x;
                s_xl[lkk + 1][row] = rl[r].y;
                s_xl[lkk + 2][row] = rl[r].z;
                s_xl[lkk + 3][row] = rl[r].w;
            }
            __syncthreads();
        }
    }

    float4 alv = *reinterpret_cast<const float4*>(&g_al[h * NN + j0 + tx * 4]);
#pragma unroll
    for (int ii = 0; ii < 2; ii++) {
        int i = i0 + ty * 2 + ii;
        int jb = j0 + tx * 4;
        float4 o;
        o.x = fmaf(0.6f, alv.x, acc[ii][0]);
        o.y = fmaf(0.6f, alv.y, acc[ii][1]);
        o.z = fmaf(0.6f, alv.z, acc[ii][2]);
        o.w = fmaf(0.6f, alv.w, acc[ii][3]);
        if (i - jb >= 0 && i - jb < 4) {
            if (i == jb + 0) o.x = -INFINITY;
            if (i == jb + 1) o.y = -INFINITY;
            if (i == jb + 2) o.z = -INFINITY;
            if (i == jb + 3) o.w = -INFINITY;
        }
        *reinterpret_cast<float4*>(&s_out[((size_t)h * NN + i) * NN + jb]) = o;
    }
}

// ---------------- softmax: warp per row, 8 rows per CTA ----------------
__global__ __launch_bounds__(256)
void gat_softmax(float* __restrict__ s) {
    const int row = blockIdx.x * 8 + (threadIdx.x >> 5);
    const int lane = threadIdx.x & 31;
    float* r = s + (size_t)row * NN;

    float4 v0 = *reinterpret_cast<const float4*>(&r[lane * 8]);
    float4 v1 = *reinterpret_cast<const float4*>(&r[lane * 8 + 4]);
    float m = fmaxf(fmaxf(fmaxf(v0.x, v0.y), fmaxf(v0.z, v0.w)),
                    fmaxf(fmaxf(v1.x, v1.y), fmaxf(v1.z, v1.w)));
#pragma unroll
    for (int o = 16; o; o >>= 1) m = fmaxf(m, __shfl_xor_sync(0xffffffffu, m, o));
    v0.x = __expf(v0.x - m); v0.y = __expf(v0.y - m);
    v0.z = __expf(v0.z - m); v0.w = __expf(v0.w - m);
    v1.x = __expf(v1.x - m); v1.y = __expf(v1.y - m);
    v1.z = __expf(v1.z - m); v1.w = __expf(v1.w - m);
    float ss = v0.x + v0.y + v0.z + v0.w + v1.x + v1.y + v1.z + v1.w;
#pragma unroll
    for (int o = 16; o; o >>= 1) ss += __shfl_xor_sync(0xffffffffu, ss, o);
    float inv = 1.f / ss;
    v0.x *= inv; v0.y *= inv; v0.z *= inv; v0.w *= inv;
    v1.x *= inv; v1.y *= inv; v1.z *= inv; v1.w *= inv;
    *reinterpret_cast<float4*>(&r[lane * 8])     = v0;
    *reinterpret_cast<float4*>(&r[lane * 8 + 4]) = v1;
}

// ---- aggregation GEMM per head: 64x64 tile, 4i x 4j per thread, FFMA2 ----
template <int D, int ACT>
__global__ __launch_bounds__(256)
void gat_agg(const float* __restrict__ a, const float* __restrict__ xl,
             const float* __restrict__ bias, float* __restrict__ out) {
    const int HD = NH * D;
    const int h = blockIdx.z;
    const int brow = blockIdx.y * 64;
    const int bcol = blockIdx.x * 64;
    const float* A = a + (size_t)h * NN * NN;
    const float* B = xl + h * D;

    __shared__ __align__(16) float As[2][32][68];   // k-major A (i contiguous)
    __shared__ __align__(16) float Ws[2][32][64];

    const int tid = threadIdx.x;
    const int tx = tid & 15;          // 4 j's at tx*4
    const int ty = tid >> 4;          // 4 i's at ty*4

    const int aIdx0 = tid * 4;                // 0..1020
    const int am0 = aIdx0 >> 5, ak0 = aIdx0 & 31;   // rows 0..31
    const int am1 = am0 + 32;                        // rows 32..63
    const int wk0 = tid >> 4;                 // rows 0..15
    const int wk1 = wk0 + 16;                 // rows 16..31
    const int wn  = (tid & 15) * 4;

    const float* Ap0 = A + (size_t)(brow + am0) * NN + ak0;
    const float* Ap1 = A + (size_t)(brow + am1) * NN + ak0;
    const float* Bp0 = B + (size_t)wk0 * HD + bcol + wn;
    const float* Bp1 = B + (size_t)wk1 * HD + bcol + wn;

    ull acc[4][2];   // [i][j-pair]
#pragma unroll
    for (int i = 0; i < 4; i++) { acc[i][0] = 0ull; acc[i][1] = 0ull; }

    {
        float4 ra0 = *reinterpret_cast<const float4*>(Ap0);
        float4 ra1 = *reinterpret_cast<const float4*>(Ap1);
        float4 rw0 = *reinterpret_cast<const float4*>(Bp0);
        float4 rw1 = *reinterpret_cast<const float4*>(Bp1);
        As[0][ak0 + 0][am0] = ra0.x;
        As[0][ak0 + 1][am0] = ra0.y;
        As[0][ak0 + 2][am0] = ra0.z;
        As[0][ak0 + 3][am0] = ra0.w;
        As[0][ak0 + 0][am1] = ra1.x;
        As[0][ak0 + 1][am1] = ra1.y;
        As[0][ak0 + 2][am1] = ra1.z;
        As[0][ak0 + 3][am1] = ra1.w;
        *reinterpret_cast<float4*>(&Ws[0][wk0][wn]) = rw0;
        *reinterpret_cast<float4*>(&Ws[0][wk1][wn]) = rw1;
    }
    __syncthreads();

    int buf = 0;
    const int nIters = NN / 32;   // 8
    for (int it = 0; it < nIters; it++) {
        const bool has_next = (it + 1) < nIters;
        float4 ra0, ra1, rw0, rw1;
        if (has_next) {
            const int ko = (it + 1) * 32;
            ra0 = *reinterpret_cast<const float4*>(Ap0 + ko);
            ra1 = *reinterpret_cast<const float4*>(Ap1 + ko);
            rw0 = *reinterpret_cast<const float4*>(Bp0 + (size_t)ko * HD);
            rw1 = *reinterpret_cast<const float4*>(Bp1 + (size_t)ko * HD);
        }
#pragma unroll
        for (int kk = 0; kk < 32; kk++) {
            float4 av = *reinterpret_cast<const float4*>(&As[buf][kk][ty * 4]);
            ulonglong2 wP = *reinterpret_cast<const ulonglong2*>(&Ws[buf][kk][tx * 4]);
            ull a0 = dupf(av.x);
            ull a1 = dupf(av.y);
            ull a2 = dupf(av.z);
            ull a3 = dupf(av.w);
            fma2(acc[0][0], a0, wP.x); fma2(acc[0][1], a0, wP.y);
            fma2(acc[1][0], a1, wP.x); fma2(acc[1][1], a1, wP.y);
            fma2(acc[2][0], a2, wP.x); fma2(acc[2][1], a2, wP.y);
            fma2(acc[3][0], a3, wP.x); fma2(acc[3][1], a3, wP.y);
        }
        if (has_next) {
            int nb = buf ^ 1;
            As[nb][ak0 + 0][am0] = ra0.x;
            As[nb][ak0 + 1][am0] = ra0.y;
            As[nb][ak0 + 2][am0] = ra0.z;
            As[nb][ak0 + 3][am0] = ra0.w;
            As[nb][ak0 + 0][am1] = ra1.x;
            As[nb][ak0 + 1][am1] = ra1.y;
            As[nb][ak0 + 2][am1] = ra1.z;
            As[nb][ak0 + 3][am1] = ra1.w;
            *reinterpret_cast<float4*>(&Ws[nb][wk0][wn]) = rw0;
            *reinterpret_cast<float4*>(&Ws[nb][wk1][wn]) = rw1;
            __syncthreads();
            buf = nb;
        }
    }

    const int n = bcol + tx * 4;
    float4 bv = *reinterpret_cast<const float4*>(&bias[h * D + n]);
#pragma unroll
    for (int i = 0; i < 4; i++) {
        int m = brow + ty * 4 + i;
        float2 lo = unpk(acc[i][0]);
        float2 hi = unpk(acc[i][1]);
        float4 o;
        o.x = lo.x + bv.x;
        o.y = lo.y + bv.y;
        o.z = hi.x + bv.z;
        o.w = hi.y + bv.w;
        if (ACT == 1) {
            o.x = o.x > 0.f ? o.x : expm1f(o.x);
            o.y = o.y > 0.f ? o.y : expm1f(o.y);
            o.z = o.z > 0.f ? o.z : expm1f(o.z);
            o.w = o.w > 0.f ? o.w : expm1f(o.w);
        }
        *reinterpret_cast<float4*>(&out[(size_t)m * HD + h * D + n]) = o;
    }
}

// ------- LayerNorm + ReLU + residual, rows 0..127; sums Wout's 16 split-K partials
__global__ __launch_bounds__(256)
void ln_residual(const float* __restrict__ bout,
                 const float* __restrict__ ln_g, const float* __restrict__ ln_b,
                 const float* __restrict__ rw,
                 const float* __restrict__ v1f, const float* __restrict__ v2f,
                 float* __restrict__ out) {
    const int i = blockIdx.x;
    const int tid = threadIdx.x;
    const int lane = tid & 31, warp = tid >> 5;
    const int MN = 128 * FDIM;
    __shared__ float s_red1[8], s_red2[8];
    __shared__ float s_mu, s_rstd;

    const float* res = (i < 64) ? (v1f + (size_t)i * FDIM)
                                : (v2f + (size_t)(i - 64) * FDIM);

    float yv[4];
    float sum = 0.f, sq = 0.f;
#pragma unroll
    for (int q = 0; q < 4; q++) {
        int c = tid + q * 256;
        float v = bout[c];
#pragma unroll
        for (int s = 0; s < 16; s++)
            v += g_part[(size_t)s * MN + i * FDIM + c];
        yv[q] = v;
        sum += v; sq += v * v;
    }
#pragma unroll
    for (int o = 16; o; o >>= 1) {
        sum += __shfl_xor_sync(0xffffffffu, sum, o);
        sq  += __shfl_xor_sync(0xffffffffu, sq,  o);
    }
    if (lane == 0) { s_red1[warp] = sum; s_red2[warp] = sq; }
    __syncthreads();
    if (tid == 0) {
        float ts = 0.f, tq = 0.f;
        for (int w = 0; w < 8; w++) { ts += s_red1[w]; tq += s_red2[w]; }
        float mu = ts / FDIM;
        float var = tq / FDIM - mu * mu;
        s_mu = mu;
        s_rstd = rsqrtf(var + 1e-5f);
    }
    __syncthreads();
    float mu = s_mu, rstd = s_rstd, w0 = rw[0];
#pragma unroll
    for (int q = 0; q < 4; q++) {
        int c = tid + q * 256;
        float v = (yv[q] - mu) * rstd * ln_g[c] + ln_b[c];
        v = fmaxf(v, 0.f);
        out[i * FDIM + c] = v + w0 * res[c];
    }
}

// ---------------- launch ----------------
extern "C" void kernel_launch(void* const* d_in, const int* in_sizes, int n_in,
                              void* d_out, int out_size) {
    (void)in_sizes; (void)n_in; (void)out_size;
    const float* v1f   = (const float*)d_in[0];
    const float* v2f   = (const float*)d_in[1];
    const float* v1fu  = (const float*)d_in[2];
    const float* v2fu  = (const float*)d_in[3];
    const float* Wl1   = (const float*)d_in[4];
    const float* bl1   = (const float*)d_in[5];
    const float* Wr1   = (const float*)d_in[6];
    const float* br1   = (const float*)d_in[7];
    const float* att1  = (const float*)d_in[8];
    const float* bias1 = (const float*)d_in[9];
    const float* Wl2   = (const float*)d_in[10];
    const float* bl2   = (const float*)d_in[11];
    const float* Wr2   = (const float*)d_in[12];
    const float* br2   = (const float*)d_in[13];
    const float* att2  = (const float*)d_in[14];
    const float* bias2 = (const float*)d_in[15];
    const float* Wout  = (const float*)d_in[16];
    const float* bout  = (const float*)d_in[17];
    const float* ln_g  = (const float*)d_in[18];
    const float* ln_b  = (const float*)d_in[19];
    const float* rw    = (const float*)d_in[20];
    float* out = (float*)d_out;

    float *xl1, *xr1, *o1, *xl2, *xr2, *o2, *sbuf;
    cudaGetSymbolAddress((void**)&xl1, g_xl1);
    cudaGetSymbolAddress((void**)&xr1, g_xr1);
    cudaGetSymbolAddress((void**)&o1,  g_o1);
    cudaGetSymbolAddress((void**)&xl2, g_xl2);
    cudaGetSymbolAddress((void**)&xr2, g_xr2);
    cudaGetSymbolAddress((void**)&o2,  g_o2);
    cudaGetSymbolAddress((void**)&sbuf, g_s);

    // ---- GAT layer 1 linear (reads the 4 inputs directly): split-K=2 -> 256 CTAs
    {
        dim3 grid(HD1 / 64, NN / 128, 4);
        gemm_pipe<<<grid, 256>>>(nullptr, v1f, v2f, v1fu, v2fu, Wl1, Wr1,
                                 NN, FDIM, HD1, 2, 1);
    }
    reduce_al1<<<NN, 256>>>(bl1, br1, att1);

    // ---- GAT layer 1 attention
    {
        dim3 grid(NN / 64, NN / 32, NH);
        gat_scores<HIDD><<<grid, 256>>>(xl1, xr1, att1, sbuf);
    }
    gat_softmax<<<NH * NN / 8, 256>>>(sbuf);
    {
        dim3 grid(HIDD / 64, NN / 64, NH);
        gat_agg<HIDD, 1><<<grid, 256>>>(sbuf, xl1, bias1, o1);
    }

    // ---- GAT layer 2 linear: split-K=4 -> 256 CTAs
    {
        dim3 grid(HD2 / 64, NN / 128, 8);
        gemm_pipe<<<grid, 256>>>(o1, nullptr, nullptr, nullptr, nullptr, Wl2, Wr2,
                                 NN, HD1, HD2, 4, 0);
    }
    reduce_al2<<<NN, 256>>>(bl2, br2, att2);

    // ---- GAT layer 2 attention
    {
        dim3 grid(NN / 64, NN / 32, NH);
        gat_scores<DD2><<<grid, 256>>>(xl2, xr2, att2, sbuf);
    }
    gat_softmax<<<NH * NN / 8, 256>>>(sbuf);
    {
        dim3 grid(DD2 / 64, NN / 64, NH);
        gat_agg<DD2, 0><<<grid, 256>>>(sbuf, xl2, bias2, o2);
    }

    // ---- Output projection rows 0..127: split-K=16 -> 256 CTAs
    {
        dim3 grid(FDIM / 64, 1, 16);
        gemm_pipe<<<grid, 256>>>(o2, nullptr, nullptr, nullptr, nullptr, Wout, Wout,
                                 128, FDIM, FDIM, 16, 0);
    }
    ln_residual<<<128, 256>>>(bout, ln_g, ln_b, rw, v1f, v2f, out);
}